// round 12
// baseline (speedup 1.0000x reference)
#include <cuda_runtime.h>
#include <cuda_bf16.h>
#include <math.h>

#define A_TOTAL 36864
#define NIN     6000
#define NOUTB   300
#define BATCH   4
#define NSEL    16384

// output layout (float32, concatenated reference tuple)
#define OFS_SCORES 0
#define OFS_LOCS   294912
#define OFS_ROIS   884736
#define OFS_RIDX   889536
#define OFS_ANCH   890736

#define TSTRIDE (9u * 8u * 512u * 32u)   // u32 elements per split-term plane

// scratch (device globals; no allocation allowed)
__device__ float  g_h[BATCH * 512 * 4096];
__device__ unsigned g_wsplit[3 * 9 * 8 * 512 * 32];   // [term][kk][cic][co][j2] bf16x2
__device__ float4 g_boxes4[BATCH * A_TOTAL];
__device__ unsigned long long g_keys[BATCH * A_TOTAL];
__device__ unsigned g_hist[BATCH * 65536];
__device__ int    g_thr[BATCH];
__device__ int    g_cnt[BATCH];
__device__ unsigned long long g_sel[BATCH * NSEL];
__device__ float4 g_bsort4[BATCH * NIN];
__device__ float  g_areas[BATCH * NIN];
__device__ int    g_keep[BATCH * NIN];

// ---------------------------------------------------------------------------
// helpers
// ---------------------------------------------------------------------------
#define SWZ(o) ((o) ^ (((o) >> 3) & 0x70))

static __device__ __forceinline__ unsigned smem_u32(const void* p) {
    unsigned a;
    asm("{ .reg .u64 t; cvta.to.shared.u64 t, %1; cvt.u32.u64 %0, t; }"
        : "=r"(a) : "l"(p));
    return a;
}
// NOTE: no "memory" clobber — __syncthreads() is the fence; mainloop has no
// C++ shared-memory reads that could be miscompiled across this.
#define STS32(addr, val) \
    asm volatile("st.shared.b32 [%0], %1;" :: "r"(addr), "r"(val))

#define LDG_F(dst, ptr) \
    asm volatile("ld.global.nc.f32 %0, [%1];" : "=f"(dst) : "l"(ptr))

#define CP_ASYNC4(dst, src) \
    asm volatile("cp.async.ca.shared.global [%0], [%1], 4;" :: "r"(dst), "l"(src))
#define CP_COMMIT() asm volatile("cp.async.commit_group;")
#define CP_WAIT0()  asm volatile("cp.async.wait_group 0;")

#define LDSM_X4(r0, r1, r2, r3, addr) \
    asm volatile("ldmatrix.sync.aligned.m8n8.x4.shared.b16 {%0,%1,%2,%3}, [%4];" \
                 : "=r"(r0), "=r"(r1), "=r"(r2), "=r"(r3) : "r"(addr))

#define MMA16816(d0, d1, d2, d3, a0, a1, a2, a3, b0, b1) \
    asm volatile("mma.sync.aligned.m16n8k16.row.col.f32.bf16.bf16.f32 " \
                 "{%0,%1,%2,%3}, {%4,%5,%6,%7}, {%8,%9}, {%0,%1,%2,%3};" \
                 : "+f"(d0), "+f"(d1), "+f"(d2), "+f"(d3) \
                 : "r"(a0), "r"(a1), "r"(a2), "r"(a3), "r"(b0), "r"(b1))

static __device__ __forceinline__ void split3(float v, unsigned short o[3]) {
    __nv_bfloat16 b0 = __float2bfloat16_rn(v);
    float f0 = __bfloat162float(b0);
    float r1 = v - f0;
    __nv_bfloat16 b1 = __float2bfloat16_rn(r1);
    float f1 = __bfloat162float(b1);
    __nv_bfloat16 b2 = __float2bfloat16_rn(r1 - f1);
    o[0] = __bfloat16_as_ushort(b0);
    o[1] = __bfloat16_as_ushort(b1);
    o[2] = __bfloat16_as_ushort(b2);
}

// ---------------------------------------------------------------------------
// weight split precompute: w[co][ci][kk] -> 3 bf16 planes [kk][cic][co][j2]
// ---------------------------------------------------------------------------
__global__ void wsplit_kernel(const float* __restrict__ w)
{
    int idx = blockIdx.x * 256 + threadIdx.x;   // 9*8*512*32 = 1,179,648 exact
    int j2  = idx & 31;
    int co  = (idx >> 5) & 511;
    int cic = (idx >> 14) & 7;
    int kk  = idx >> 17;
    if (kk >= 9) return;
    int ci = cic * 64 + j2 * 2;
    float v0 = w[((size_t)co * 512 + ci) * 9 + kk];
    float v1 = w[((size_t)co * 512 + ci + 1) * 9 + kk];
    unsigned short h[3], g[3];
    split3(v0, h);
    split3(v1, g);
    unsigned base = (((unsigned)kk * 8 + cic) * 512 + co) * 32 + j2;
#pragma unroll
    for (int t = 0; t < 3; t++)
        g_wsplit[t * TSTRIDE + base] = (unsigned)h[t] | ((unsigned)g[t] << 16);
}

__global__ void zerohist_kernel()
{
    g_hist[blockIdx.x * 1024 + threadIdx.x] = 0u;
}

// ---------------------------------------------------------------------------
// 3x3 conv 512->512 + bias + relu via mma.sync bf16 6-term emulated-fp32.
// CTA: 512 threads / 16 warps. M=128 co (blockIdx.x), N=128 px (2 rows).
// Warp tile m32n32. 72 chunks of 64 ci at fixed (dy,dx), double-buffered.
// A staged by cp.async (pre-split copy); B x-values LDG'd into registers
// BEFORE the MMA section (latency hidden), converted + STS'd after it.
// RZ-bias mitigation: zero-started partial P per phase, rn-FADD folds.
// ---------------------------------------------------------------------------
__global__ __launch_bounds__(512, 1) void conv_mma_kernel(
    const float* __restrict__ x, const float* __restrict__ bias)
{
    extern __shared__ __align__(16) char dsm[];
    const unsigned raw  = smem_u32(dsm);
    const unsigned base = (raw + 1023u) & ~1023u;  // 1024-aligned tiles

    const int tid = threadIdx.x;
    const int wid = tid >> 5;
    const int lid = tid & 31;
    const int m0  = blockIdx.x * 128;
    const int b   = blockIdx.y >> 5;
    const int y0  = (blockIdx.y & 31) * 2;
    const float* xb = x + (size_t)b * 512 * 4096;

    const int mh = wid >> 2;            // co block of 32 (0..3)
    const int nq = wid & 3;             // px block of 32 (0..3)
    const int rlow = lid & 15;
    const int chalf = (lid >> 4) * 16;

    float acc[2][4][4];
    float P[2][4][4];
#pragma unroll
    for (int i = 0; i < 2; i++)
#pragma unroll
        for (int j = 0; j < 4; j++)
#pragma unroll
            for (int r = 0; r < 4; r++) { acc[i][j][r] = 0.f; P[i][j][r] = 0.f; }

    float pv0[8], pv1[8];
    bool  pok[8];

    // buffer set layout (per set, stride 98304): B0,B1,B2 @ 0/16K/32K, A0..A2 @ 48K/64K/80K
    auto stageA = [&](int c, int s) {
        const int kk  = c >> 3;
        const int cic = c & 7;
        const unsigned sb = base + (unsigned)s * 98304u;
        const unsigned* wp = g_wsplit + (((unsigned)kk * 8 + cic) * 512) * 32;
#pragma unroll
        for (int it = 0; it < 8; it++) {
            int idx = tid + it * 512;
            int co = idx >> 5, j2 = idx & 31;
            unsigned off = SWZ((unsigned)(co * 128 + j2 * 4));
            const unsigned* sp = wp + (unsigned)(m0 + co) * 32 + j2;
            CP_ASYNC4(sb + 49152u + off, sp);
            CP_ASYNC4(sb + 65536u + off, sp + TSTRIDE);
            CP_ASYNC4(sb + 81920u + off, sp + 2 * TSTRIDE);
        }
    };

    auto prefB = [&](int c) {
        const int kk  = c >> 3;
        const int cic = c & 7;
        const int dy  = kk / 3, dx = kk - dy * 3;
        const int ci0 = cic * 64;
#pragma unroll
        for (int it = 0; it < 8; it++) {
            int idx = tid + it * 512;
            int px = idx & 127, j2 = idx >> 7;
            int yy = y0 + (px >> 6) + dy - 1;
            int xx = (px & 63) + dx - 1;
            pok[it] = ((unsigned)yy < 64u) && ((unsigned)xx < 64u);
            int yc = yy < 0 ? 0 : (yy > 63 ? 63 : yy);
            int xc = xx < 0 ? 0 : (xx > 63 ? 63 : xx);
            const float* sp = xb + ((size_t)(ci0 + j2 * 2) * 64 + yc) * 64 + xc;
            LDG_F(pv0[it], sp);
            LDG_F(pv1[it], sp + 4096);
        }
    };

    auto storeB = [&](int s) {
        const unsigned sb = base + (unsigned)s * 98304u;
#pragma unroll
        for (int it = 0; it < 8; it++) {
            int idx = tid + it * 512;
            int px = idx & 127, j2 = idx >> 7;
            float v0 = pok[it] ? pv0[it] : 0.f;
            float v1 = pok[it] ? pv1[it] : 0.f;
            unsigned short h0[3], h1[3];
            split3(v0, h0);
            split3(v1, h1);
            unsigned off = SWZ((unsigned)(px * 128 + j2 * 4));
            STS32(sb + off,          (unsigned)h0[0] | ((unsigned)h1[0] << 16));
            STS32(sb + 16384u + off, (unsigned)h0[1] | ((unsigned)h1[1] << 16));
            STS32(sb + 32768u + off, (unsigned)h0[2] | ((unsigned)h1[2] << 16));
        }
    };

    // one k16 step for term pair (Ab, Bb) accumulating into P
    auto k16step = [&](unsigned Ab, unsigned Bb, int ks) {
        unsigned bf[2][4], af[2][4];
#pragma unroll
        for (int bn = 0; bn < 2; bn++) {
            unsigned baddr = Bb +
                SWZ((unsigned)((nq * 32 + bn * 16 + rlow) * 128 + ks * 32 + chalf));
            LDSM_X4(bf[bn][0], bf[bn][1], bf[bn][2], bf[bn][3], baddr);
        }
#pragma unroll
        for (int mt = 0; mt < 2; mt++) {
            unsigned aaddr = Ab +
                SWZ((unsigned)((mh * 32 + mt * 16 + rlow) * 128 + ks * 32 + chalf));
            LDSM_X4(af[mt][0], af[mt][1], af[mt][2], af[mt][3], aaddr);
        }
#pragma unroll
        for (int mt = 0; mt < 2; mt++)
#pragma unroll
            for (int bn = 0; bn < 2; bn++) {
                MMA16816(P[mt][bn*2][0], P[mt][bn*2][1], P[mt][bn*2][2], P[mt][bn*2][3],
                         af[mt][0], af[mt][1], af[mt][2], af[mt][3],
                         bf[bn][0], bf[bn][2]);
                MMA16816(P[mt][bn*2+1][0], P[mt][bn*2+1][1], P[mt][bn*2+1][2], P[mt][bn*2+1][3],
                         af[mt][0], af[mt][1], af[mt][2], af[mt][3],
                         bf[bn][1], bf[bn][3]);
            }
    };

    auto drain = [&]() {
#pragma unroll
        for (int i = 0; i < 2; i++)
#pragma unroll
            for (int j = 0; j < 4; j++)
#pragma unroll
                for (int r = 0; r < 4; r++) { acc[i][j][r] += P[i][j][r]; P[i][j][r] = 0.f; }
    };

    // prologue: fill buffer 0
    stageA(0, 0);
    CP_COMMIT();
    prefB(0);
    storeB(0);
    CP_WAIT0();
    __syncthreads();

    for (int c = 0; c < 72; c++) {
        const int s = c & 1;
        if (c + 1 < 72) {
            stageA(c + 1, s ^ 1);
            CP_COMMIT();
            prefB(c + 1);     // LDGs issued now; consumed after MMA section
        }

        const unsigned sb = base + (unsigned)s * 98304u;
        // phase A: big term A0*B0
#pragma unroll
        for (int ks = 0; ks < 4; ks++)
            k16step(sb + 49152u, sb, ks);
        drain();
        // phase B: small cross terms
        const int TA[5] = {0, 1, 1, 0, 2};
        const int TB[5] = {1, 0, 1, 2, 0};
#pragma unroll
        for (int t = 0; t < 5; t++) {
            const unsigned Ab = sb + 49152u + (unsigned)TA[t] * 16384u;
            const unsigned Bb = sb + (unsigned)TB[t] * 16384u;
#pragma unroll
            for (int ks = 0; ks < 4; ks++)
                k16step(Ab, Bb, ks);
        }
        drain();

        if (c + 1 < 72) {
            storeB(s ^ 1);
            CP_WAIT0();
        }
        __syncthreads();
    }

    // epilogue: accs -> bias+relu -> smem transpose [co][px] (row stride 132 f32)
    {
        const int gr = lid >> 2;
        const int qc = lid & 3;
#pragma unroll
        for (int mt = 0; mt < 2; mt++) {
#pragma unroll
            for (int hi = 0; hi < 2; hi++) {
                int co_l = mh * 32 + mt * 16 + hi * 8 + gr;
                float bb = bias[m0 + co_l];
                unsigned trow = base + (unsigned)co_l * 528u;
#pragma unroll
                for (int nn = 0; nn < 4; nn++) {
#pragma unroll
                    for (int lo = 0; lo < 2; lo++) {
                        int px = nq * 32 + nn * 8 + qc * 2 + lo;
                        float v = acc[mt][nn][hi * 2 + lo] + bb;
                        v = v > 0.f ? v : 0.f;
                        STS32(trow + (unsigned)px * 4u, __float_as_uint(v));
                    }
                }
            }
        }
    }
    __syncthreads();

    // coalesced write-out: g_h[b][m0+co][y0 + px/64][px%64]
    for (int idx = tid; idx < 4096; idx += 512) {
        int co = idx >> 5;
        int p4 = (idx & 31) * 4;
        unsigned a0, a1, a2, a3;
        asm volatile("ld.shared.v4.b32 {%0,%1,%2,%3}, [%4];"
                     : "=r"(a0), "=r"(a1), "=r"(a2), "=r"(a3)
                     : "r"(base + (unsigned)co * 528u + (unsigned)p4 * 4u));
        float* dst = g_h + (((size_t)b * 512 + m0 + co) * 64 + y0 + (p4 >> 6)) * 64
                     + (p4 & 63);
        *(float4*)dst = make_float4(__uint_as_float(a0), __uint_as_float(a1),
                                    __uint_as_float(a2), __uint_as_float(a3));
    }
}

// ---------------------------------------------------------------------------
// 1x1 heads + softmax fg + box decode + sort keys + score-bucket histogram
// ---------------------------------------------------------------------------
__global__ __launch_bounds__(128) void heads_kernel(
    const float* __restrict__ sw, const float* __restrict__ sb,
    const float* __restrict__ lw, const float* __restrict__ lb,
    float* __restrict__ out)
{
    __shared__ float ws[64 * 54];
    const int tid = threadIdx.x;
    const int pg  = blockIdx.x * 128 + tid;
    const int b   = pg >> 12;
    const int pix = pg & 4095;

    float acc[54];
#pragma unroll
    for (int c = 0; c < 54; c++) acc[c] = 0.f;

    for (int cc = 0; cc < 512; cc += 64) {
        for (int idx = tid; idx < 64 * 54; idx += 128) {
            int ci = idx / 54;
            int c  = idx - ci * 54;
            ws[idx] = (c < 18) ? sw[c * 512 + cc + ci]
                               : lw[(c - 18) * 512 + cc + ci];
        }
        __syncthreads();
#pragma unroll 4
        for (int ci = 0; ci < 64; ci++) {
            float v = g_h[((size_t)(b * 512 + cc + ci)) * 4096 + pix];
#pragma unroll
            for (int c = 0; c < 54; c++) acc[c] += v * ws[ci * 54 + c];
        }
        __syncthreads();
    }

    const int y  = pix >> 6;
    const int xq = pix & 63;
    const float sy = (float)(y * 16);
    const float sx = (float)(xq * 16);

#pragma unroll
    for (int k = 0; k < 9; k++) {
        const double RR[3] = {0.5, 1.0, 2.0};
        const double SS[3] = {8.0, 16.0, 32.0};
        double rr = RR[k / 3], ss = SS[k % 3];
        double hh = 16.0 * ss * sqrt(rr);
        double wd = 16.0 * ss * sqrt(1.0 / rr);
        float by1 = (float)(8.0 - hh * 0.5), bx1 = (float)(8.0 - wd * 0.5);
        float by2 = (float)(8.0 + hh * 0.5), bx2 = (float)(8.0 + wd * 0.5);
        float ay1 = sy + by1, ax1 = sx + bx1, ay2 = sy + by2, ax2 = sx + bx2;

        const int a = pix * 9 + k;
        if (b == 0) {
            float* ap = out + OFS_ANCH + (size_t)a * 4;
            ap[0] = ay1; ap[1] = ax1; ap[2] = ay2; ap[3] = ax2;
        }

        float s0 = acc[k * 2 + 0] + sb[k * 2 + 0];
        float s1 = acc[k * 2 + 1] + sb[k * 2 + 1];
        out[OFS_SCORES + (size_t)b * 73728 + (size_t)a * 2 + 0] = s0;
        out[OFS_SCORES + (size_t)b * 73728 + (size_t)a * 2 + 1] = s1;

        float d0 = acc[18 + k * 4 + 0] + lb[k * 4 + 0];
        float d1 = acc[18 + k * 4 + 1] + lb[k * 4 + 1];
        float d2 = acc[18 + k * 4 + 2] + lb[k * 4 + 2];
        float d3 = acc[18 + k * 4 + 3] + lb[k * 4 + 3];
        float* lp = out + OFS_LOCS + (size_t)b * 147456 + (size_t)a * 4;
        lp[0] = d0; lp[1] = d1; lp[2] = d2; lp[3] = d3;

        float ah = ay2 - ay1, aw = ax2 - ax1;
        float cy = ay1 + 0.5f * ah, cx = ax1 + 0.5f * aw;
        float cty = d0 * ah + cy, ctx = d1 * aw + cx;
        float th = expf(d2) * ah, tw = expf(d3) * aw;
        float cy1 = fminf(fmaxf(cty - 0.5f * th, 0.f), 1024.f);
        float cy2 = fminf(fmaxf(cty + 0.5f * th, 0.f), 1024.f);
        float cx1 = fminf(fmaxf(ctx - 0.5f * tw, 0.f), 1024.f);
        float cx2 = fminf(fmaxf(ctx + 0.5f * tw, 0.f), 1024.f);
        bool valid = (cy2 - cy1 >= 16.f) && (cx2 - cx1 >= 16.f);

        float m = fmaxf(s0, s1);
        float e0 = expf(s0 - m), e1 = expf(s1 - m);
        float p1 = e1 / (e0 + e1);

        g_boxes4[(size_t)b * A_TOTAL + a] = make_float4(cy1, cx1, cy2, cx2);

        unsigned long long key;
        if (valid) {
            unsigned u = __float_as_uint(p1);
            u = (u & 0x80000000u) ? ~u : (u | 0x80000000u);
            key = ((unsigned long long)(~u) << 32) | (unsigned)a;
        } else {
            key = (0xFF800000ull << 32) | (unsigned)a;  // -inf score
        }
        g_keys[(size_t)b * A_TOTAL + a] = key;
        atomicAdd(&g_hist[b * 65536 + (unsigned)(key >> 48)], 1u);
    }
}

// find bucket threshold covering rank NIN; also reset count + pad sel buffer
__global__ __launch_bounds__(1024) void select_kernel()
{
    const int b = blockIdx.x, tid = threadIdx.x;
    __shared__ int part[1024];
    const unsigned* h = g_hist + b * 65536;
    int s = 0;
    for (int k = 0; k < 64; k++) s += (int)h[tid * 64 + k];
    part[tid] = s;
    __syncthreads();
    for (int off = 1; off < 1024; off <<= 1) {
        int v = (tid >= off) ? part[tid - off] : 0;
        __syncthreads();
        part[tid] += v;
        __syncthreads();
    }
    int incl = part[tid];
    int excl = incl - s;
    if (excl < NIN && incl >= NIN) {
        int c = excl, T = tid * 64 + 63;
        for (int k = 0; k < 64; k++) {
            c += (int)h[tid * 64 + k];
            if (c >= NIN) { T = tid * 64 + k; break; }
        }
        g_thr[b] = T;
    }
    if (tid == 0) g_cnt[b] = 0;
    for (int i = tid; i < NSEL; i += 1024) g_sel[b * NSEL + i] = ~0ull;
}

__global__ void compact_sel_kernel()
{
    int i = blockIdx.x * 256 + threadIdx.x;
    int b = blockIdx.y;
    if (i >= A_TOTAL) return;
    unsigned long long key = g_keys[(size_t)b * A_TOTAL + i];
    if ((int)(unsigned)(key >> 48) <= g_thr[b]) {
        int p = atomicAdd(&g_cnt[b], 1);
        if (p < NSEL) g_sel[b * NSEL + p] = key;
    }
}

// per-batch smem bitonic sort of <=16384 selected keys, then gather top-6000
__global__ __launch_bounds__(1024) void sortsel_kernel()
{
    const int b = blockIdx.x, tid = threadIdx.x;
    extern __shared__ unsigned long long s[];
    for (int i = tid; i < NSEL; i += 1024) s[i] = g_sel[b * NSEL + i];
    __syncthreads();
    for (int k = 2; k <= NSEL; k <<= 1) {
        for (int j = k >> 1; j > 0; j >>= 1) {
            for (int t = tid; t < NSEL; t += 1024) {
                int ixj = t ^ j;
                if (ixj > t) {
                    unsigned long long A = s[t], B = s[ixj];
                    bool up = ((t & k) == 0);
                    if ((A > B) == up) { s[t] = B; s[ixj] = A; }
                }
            }
            __syncthreads();
        }
    }
    for (int i = tid; i < NIN; i += 1024) {
        unsigned long long key = s[i];
        unsigned idx = (unsigned)key;
        float4 bx = g_boxes4[(size_t)b * A_TOTAL + idx];
        g_bsort4[b * NIN + i] = bx;
        g_areas[b * NIN + i] = (bx.z - bx.x) * (bx.w - bx.y);
        g_keep[b * NIN + i] = (int)((key >> 63) == 0);
    }
}

// sequential greedy NMS, all-smem + register-resident owned boxes
__global__ __launch_bounds__(1024) void nms_kernel()
{
    const int b = blockIdx.x, tid = threadIdx.x;
    extern __shared__ char nsm[];
    float4* bsh = (float4*)nsm;                          // 96000 B
    float* ash = (float*)(nsm + 96000);                  // 24000 B
    unsigned char* ksh = (unsigned char*)(nsm + 120000); // 6000 B

    for (int i = tid; i < NIN; i += 1024) {
        bsh[i] = g_bsort4[b * NIN + i];
        ash[i] = g_areas[b * NIN + i];
        ksh[i] = (unsigned char)g_keep[b * NIN + i];
    }
    __syncthreads();

    float4 myb[6]; float mya[6]; int myk[6];
#pragma unroll
    for (int e = 0; e < 6; e++) {
        int j = tid * 6 + e;
        if (j < NIN) { myb[e] = bsh[j]; mya[e] = ash[j]; myk[e] = (int)ksh[j]; }
        else myk[e] = 0;
    }

    for (int i = 0; i < NIN - 1; i++) {
        if (ksh[i]) {
            float4 bi = bsh[i];
            float ai = ash[i];
#pragma unroll
            for (int e = 0; e < 6; e++) {
                int j = tid * 6 + e;
                if (myk[e] && j > i) {
                    float yy1 = fmaxf(bi.x, myb[e].x);
                    float xx1 = fmaxf(bi.y, myb[e].y);
                    float yy2 = fminf(bi.z, myb[e].z);
                    float xx2 = fminf(bi.w, myb[e].w);
                    float inter = fmaxf(yy2 - yy1, 0.f) * fmaxf(xx2 - xx1, 0.f);
                    float iou = inter / (ai + mya[e] - inter + 1e-9f);
                    if (iou > 0.7f) { myk[e] = 0; ksh[j] = 0; }
                }
            }
            __syncthreads();
        }
    }
    for (int i = tid; i < NIN; i += 1024) g_keep[b * NIN + i] = (int)ksh[i];
}

// compact kept boxes into first 300 rows; zero-fill the rest; roi_indices
__global__ __launch_bounds__(1024) void compact_kernel(float* __restrict__ out)
{
    const int b = blockIdx.x;
    const int tid = threadIdx.x;
    __shared__ int csum[1024];

    const int base = tid * 6;
    int local[6];
    int cnt = 0;
#pragma unroll
    for (int e = 0; e < 6; e++) {
        int i = base + e;
        int k = (i < NIN) ? g_keep[b * NIN + i] : 0;
        local[e] = k;
        cnt += k;
    }
    csum[tid] = cnt;
    __syncthreads();
    for (int off = 1; off < 1024; off <<= 1) {
        int v = (tid >= off) ? csum[tid - off] : 0;
        __syncthreads();
        csum[tid] += v;
        __syncthreads();
    }
    int rank = csum[tid] - cnt;

    float* rois = out + OFS_ROIS + (size_t)b * 1200;
    for (int i = tid; i < 1200; i += 1024) rois[i] = 0.f;
    float* ridx = out + OFS_RIDX + (size_t)b * 300;
    for (int i = tid; i < 300; i += 1024) ridx[i] = (float)b;
    __syncthreads();

    int r = rank;
#pragma unroll
    for (int e = 0; e < 6; e++) {
        int i = base + e;
        if (i < NIN && local[e]) {
            if (r < NOUTB) {
                float4 bx = g_bsort4[b * NIN + i];
                rois[r * 4 + 0] = bx.x;
                rois[r * 4 + 1] = bx.y;
                rois[r * 4 + 2] = bx.z;
                rois[r * 4 + 3] = bx.w;
            }
            r++;
        }
    }
}

extern "C" void kernel_launch(void* const* d_in, const int* in_sizes, int n_in,
                              void* d_out, int out_size)
{
    const float* x       = (const float*)d_in[0];
    const float* conv_w  = (const float*)d_in[1];
    const float* conv_b  = (const float*)d_in[2];
    const float* score_w = (const float*)d_in[3];
    const float* score_b = (const float*)d_in[4];
    const float* loc_w   = (const float*)d_in[5];
    const float* loc_b   = (const float*)d_in[6];
    float* out = (float*)d_out;

    const int CONV_SMEM = 1024 + 2 * 98304;   // align slack + 2 buffer sets
    cudaFuncSetAttribute(conv_mma_kernel,
        cudaFuncAttributeMaxDynamicSharedMemorySize, CONV_SMEM);
    cudaFuncSetAttribute(sortsel_kernel,
        cudaFuncAttributeMaxDynamicSharedMemorySize, NSEL * 8);
    cudaFuncSetAttribute(nms_kernel,
        cudaFuncAttributeMaxDynamicSharedMemorySize, 126016);

    wsplit_kernel<<<4608, 256>>>(conv_w);
    zerohist_kernel<<<256, 1024>>>();
    conv_mma_kernel<<<dim3(4, 128), 512, CONV_SMEM>>>(x, conv_b);
    heads_kernel<<<128, 128>>>(score_w, score_b, loc_w, loc_b, out);
    select_kernel<<<BATCH, 1024>>>();
    compact_sel_kernel<<<dim3(144, BATCH), 256>>>();
    sortsel_kernel<<<BATCH, 1024, NSEL * 8>>>();
    nms_kernel<<<BATCH, 1024, 126016>>>();
    compact_kernel<<<BATCH, 1024>>>(out);
}

// round 13
// speedup vs baseline: 1.7015x; 1.7015x over previous
#include <cuda_runtime.h>
#include <cuda_bf16.h>
#include <math.h>

#define A_TOTAL 36864
#define NIN     6000
#define NOUTB   300
#define BATCH   4
#define NSEL    16384

// output layout (float32, concatenated reference tuple)
#define OFS_SCORES 0
#define OFS_LOCS   294912
#define OFS_ROIS   884736
#define OFS_RIDX   889536
#define OFS_ANCH   890736

#define TSTRIDE (9u * 8u * 512u * 32u)   // u32 elements per split-term plane

// scratch (device globals; no allocation allowed)
__device__ float  g_h[BATCH * 512 * 4096];
__device__ unsigned g_wsplit[3 * 9 * 8 * 512 * 32];   // [term][kk][cic][co][j2] bf16x2
__device__ unsigned short g_xs0[BATCH * 4096 * 512];  // channel-last bf16 term planes
__device__ unsigned short g_xs1[BATCH * 4096 * 512];
__device__ unsigned short g_xs2[BATCH * 4096 * 512];
__device__ float4 g_boxes4[BATCH * A_TOTAL];
__device__ unsigned long long g_keys[BATCH * A_TOTAL];
__device__ unsigned g_hist[BATCH * 65536];
__device__ int    g_thr[BATCH];
__device__ int    g_cnt[BATCH];
__device__ unsigned long long g_sel[BATCH * NSEL];
__device__ float4 g_bsort4[BATCH * NIN];
__device__ float  g_areas[BATCH * NIN];
__device__ int    g_keep[BATCH * NIN];

// ---------------------------------------------------------------------------
// helpers
// ---------------------------------------------------------------------------
#define SWZ(o) ((o) ^ (((o) >> 3) & 0x70))

static __device__ __forceinline__ unsigned smem_u32(const void* p) {
    unsigned a;
    asm("{ .reg .u64 t; cvta.to.shared.u64 t, %1; cvt.u32.u64 %0, t; }"
        : "=r"(a) : "l"(p));
    return a;
}
// no "memory" clobber — __syncthreads() is the fence
#define STS32(addr, val) \
    asm volatile("st.shared.b32 [%0], %1;" :: "r"(addr), "r"(val))

#define CP16(dst, src) \
    asm volatile("cp.async.cg.shared.global [%0], [%1], 16;" \
                 :: "r"(dst), "l"(src))
#define CP16Z(dst, src, sz) \
    asm volatile("cp.async.cg.shared.global [%0], [%1], 16, %2;" \
                 :: "r"(dst), "l"(src), "r"(sz))
#define CP_COMMIT() asm volatile("cp.async.commit_group;")
#define CP_WAIT0()  asm volatile("cp.async.wait_group 0;")

#define LDSM_X4(r0, r1, r2, r3, addr) \
    asm volatile("ldmatrix.sync.aligned.m8n8.x4.shared.b16 {%0,%1,%2,%3}, [%4];" \
                 : "=r"(r0), "=r"(r1), "=r"(r2), "=r"(r3) : "r"(addr))

#define MMA16816(d0, d1, d2, d3, a0, a1, a2, a3, b0, b1) \
    asm volatile("mma.sync.aligned.m16n8k16.row.col.f32.bf16.bf16.f32 " \
                 "{%0,%1,%2,%3}, {%4,%5,%6,%7}, {%8,%9}, {%0,%1,%2,%3};" \
                 : "+f"(d0), "+f"(d1), "+f"(d2), "+f"(d3) \
                 : "r"(a0), "r"(a1), "r"(a2), "r"(a3), "r"(b0), "r"(b1))

static __device__ __forceinline__ void split3(float v, unsigned short o[3]) {
    __nv_bfloat16 b0 = __float2bfloat16_rn(v);
    float f0 = __bfloat162float(b0);
    float r1 = v - f0;
    __nv_bfloat16 b1 = __float2bfloat16_rn(r1);
    float f1 = __bfloat162float(b1);
    __nv_bfloat16 b2 = __float2bfloat16_rn(r1 - f1);
    o[0] = __bfloat16_as_ushort(b0);
    o[1] = __bfloat16_as_ushort(b1);
    o[2] = __bfloat16_as_ushort(b2);
}

// ---------------------------------------------------------------------------
// weight split precompute: w[co][ci][kk] -> 3 bf16 planes [kk][cic][co][j2]
// ---------------------------------------------------------------------------
__global__ void wsplit_kernel(const float* __restrict__ w)
{
    int idx = blockIdx.x * 256 + threadIdx.x;   // 9*8*512*32 = 1,179,648 exact
    int j2  = idx & 31;
    int co  = (idx >> 5) & 511;
    int cic = (idx >> 14) & 7;
    int kk  = idx >> 17;
    if (kk >= 9) return;
    int ci = cic * 64 + j2 * 2;
    float v0 = w[((size_t)co * 512 + ci) * 9 + kk];
    float v1 = w[((size_t)co * 512 + ci + 1) * 9 + kk];
    unsigned short h[3], g[3];
    split3(v0, h);
    split3(v1, g);
    unsigned base = (((unsigned)kk * 8 + cic) * 512 + co) * 32 + j2;
#pragma unroll
    for (int t = 0; t < 3; t++)
        g_wsplit[t * TSTRIDE + base] = (unsigned)h[t] | ((unsigned)g[t] << 16);
}

// ---------------------------------------------------------------------------
// input split precompute: x[b][ci][y][x] f32 -> channel-last bf16 planes
// g_xs{0,1,2}[((b*64+y)*64+x)*512 + ci].  Tile transpose through smem.
// ---------------------------------------------------------------------------
__global__ __launch_bounds__(256) void xsplit_kernel(const float* __restrict__ x)
{
    __shared__ float t[32][33];
    const int bid = blockIdx.x;          // 4 * 16 * 128 = 8192 blocks
    const int pt  = bid & 127;           // pixel tile (32 px)
    const int ct  = (bid >> 7) & 15;     // ci tile (32 ci)
    const int b   = bid >> 11;
    const int tid = threadIdx.x;

    const float* xp = x + ((size_t)b * 512 + ct * 32) * 4096 + pt * 32;
#pragma unroll
    for (int k = 0; k < 4; k++) {
        int l = tid + k * 256;
        int ci_l = l >> 5, px_l = l & 31;
        t[ci_l][px_l] = xp[(size_t)ci_l * 4096 + px_l];
    }
    __syncthreads();
#pragma unroll
    for (int k = 0; k < 4; k++) {
        int l = tid + k * 256;
        int px_l = l >> 5, ci_l = l & 31;
        float v = t[ci_l][px_l];
        unsigned short h[3];
        split3(v, h);
        size_t o = ((size_t)b * 4096 + pt * 32 + px_l) * 512 + ct * 32 + ci_l;
        g_xs0[o] = h[0];
        g_xs1[o] = h[1];
        g_xs2[o] = h[2];
    }
}

__global__ void zerohist_kernel()
{
    g_hist[blockIdx.x * 1024 + threadIdx.x] = 0u;
}

// ---------------------------------------------------------------------------
// 3x3 conv 512->512 + bias + relu via mma.sync bf16 6-term emulated-fp32.
// CTA: 512 threads / 16 warps. M=128 co (blockIdx.x), N=128 px (2 rows).
// Warp tile m32n32. 72 chunks of 64 ci at fixed (dy,dx), double-buffered.
// All staging is pure 16B cp.async from pre-split operands (zero registers,
// zero ALU); boundary pixels zero-filled via src-size=0.
// RZ-bias mitigation: zero-started partial P per phase, rn-FADD folds.
// ---------------------------------------------------------------------------
__global__ __launch_bounds__(512, 1) void conv_mma_kernel(
    const float* __restrict__ x, const float* __restrict__ bias)
{
    extern __shared__ __align__(16) char dsm[];
    const unsigned raw  = smem_u32(dsm);
    const unsigned base = (raw + 1023u) & ~1023u;  // 1024-aligned tiles

    const int tid = threadIdx.x;
    const int wid = tid >> 5;
    const int lid = tid & 31;
    const int m0  = blockIdx.x * 128;
    const int b   = blockIdx.y >> 5;
    const int y0  = (blockIdx.y & 31) * 2;

    const int mh = wid >> 2;            // co block of 32 (0..3)
    const int nq = wid & 3;             // px block of 32 (0..3)
    const int rlow = lid & 15;
    const int chalf = (lid >> 4) * 16;

    float acc[2][4][4];
    float P[2][4][4];
#pragma unroll
    for (int i = 0; i < 2; i++)
#pragma unroll
        for (int j = 0; j < 4; j++)
#pragma unroll
            for (int r = 0; r < 4; r++) { acc[i][j][r] = 0.f; P[i][j][r] = 0.f; }

    // buffer set layout (per set, stride 98304): B0,B1,B2 @ 0/16K/32K, A0..A2 @ 48K/64K/80K
    auto stageAB = [&](int c, int s) {
        const int kk  = c >> 3;
        const int cic = c & 7;
        const int dy  = kk / 3, dx = kk - dy * 3;
        const int ci0 = cic * 64;
        const unsigned sb = base + (unsigned)s * 98304u;
        // A: pure copy of pre-split weights (ci-contiguous 128B per co row)
        const unsigned* wp = g_wsplit + ((unsigned)(kk * 8 + cic) * 512 + m0) * 32;
#pragma unroll
        for (int it = 0; it < 2; it++) {
            int idx = tid + it * 512;
            int co = idx >> 3, seg = idx & 7;
            unsigned off = SWZ((unsigned)(co * 128 + seg * 16));
            const unsigned* sp = wp + co * 32 + seg * 4;
            CP16(sb + 49152u + off, sp);
            CP16(sb + 65536u + off, sp + TSTRIDE);
            CP16(sb + 81920u + off, sp + 2 * TSTRIDE);
        }
        // B: pure copy of channel-last pre-split input rows (128B per px)
#pragma unroll
        for (int it = 0; it < 2; it++) {
            int idx = tid + it * 512;
            int px = idx >> 3, seg = idx & 7;
            int yy = y0 + (px >> 6) + dy - 1;
            int xx = (px & 63) + dx - 1;
            bool ok = ((unsigned)yy < 64u) && ((unsigned)xx < 64u);
            int yc = ok ? yy : 0, xc = ok ? xx : 0;
            size_t po = ((size_t)b * 4096 + (size_t)yc * 64 + xc) * 512
                        + ci0 + seg * 8;
            unsigned off = SWZ((unsigned)(px * 128 + seg * 16));
            int sz = ok ? 16 : 0;
            CP16Z(sb + off,          g_xs0 + po, sz);
            CP16Z(sb + 16384u + off, g_xs1 + po, sz);
            CP16Z(sb + 32768u + off, g_xs2 + po, sz);
        }
    };

    // one k16 step for term pair (Ab, Bb) accumulating into P
    auto k16step = [&](unsigned Ab, unsigned Bb, int ks) {
        unsigned bf[2][4], af[2][4];
#pragma unroll
        for (int bn = 0; bn < 2; bn++) {
            unsigned baddr = Bb +
                SWZ((unsigned)((nq * 32 + bn * 16 + rlow) * 128 + ks * 32 + chalf));
            LDSM_X4(bf[bn][0], bf[bn][1], bf[bn][2], bf[bn][3], baddr);
        }
#pragma unroll
        for (int mt = 0; mt < 2; mt++) {
            unsigned aaddr = Ab +
                SWZ((unsigned)((mh * 32 + mt * 16 + rlow) * 128 + ks * 32 + chalf));
            LDSM_X4(af[mt][0], af[mt][1], af[mt][2], af[mt][3], aaddr);
        }
#pragma unroll
        for (int mt = 0; mt < 2; mt++)
#pragma unroll
            for (int bn = 0; bn < 2; bn++) {
                MMA16816(P[mt][bn*2][0], P[mt][bn*2][1], P[mt][bn*2][2], P[mt][bn*2][3],
                         af[mt][0], af[mt][1], af[mt][2], af[mt][3],
                         bf[bn][0], bf[bn][2]);
                MMA16816(P[mt][bn*2+1][0], P[mt][bn*2+1][1], P[mt][bn*2+1][2], P[mt][bn*2+1][3],
                         af[mt][0], af[mt][1], af[mt][2], af[mt][3],
                         bf[bn][1], bf[bn][3]);
            }
    };

    auto drain = [&]() {
#pragma unroll
        for (int i = 0; i < 2; i++)
#pragma unroll
            for (int j = 0; j < 4; j++)
#pragma unroll
                for (int r = 0; r < 4; r++) { acc[i][j][r] += P[i][j][r]; P[i][j][r] = 0.f; }
    };

    // prologue: fill buffer 0
    stageAB(0, 0);
    CP_COMMIT();
    CP_WAIT0();
    __syncthreads();

    for (int c = 0; c < 72; c++) {
        const int s = c & 1;
        if (c + 1 < 72) {
            stageAB(c + 1, s ^ 1);   // async; overlaps with MMA below
            CP_COMMIT();
        }

        const unsigned sb = base + (unsigned)s * 98304u;
        // phase A: big term A0*B0
#pragma unroll
        for (int ks = 0; ks < 4; ks++)
            k16step(sb + 49152u, sb, ks);
        drain();
        // phase B: small cross terms
        const int TA[5] = {0, 1, 1, 0, 2};
        const int TB[5] = {1, 0, 1, 2, 0};
#pragma unroll
        for (int t = 0; t < 5; t++) {
            const unsigned Ab = sb + 49152u + (unsigned)TA[t] * 16384u;
            const unsigned Bb = sb + (unsigned)TB[t] * 16384u;
#pragma unroll
            for (int ks = 0; ks < 4; ks++)
                k16step(Ab, Bb, ks);
        }
        drain();

        if (c + 1 < 72) CP_WAIT0();
        __syncthreads();
    }

    // epilogue: accs -> bias+relu -> smem transpose [co][px] (row stride 132 f32)
    {
        const int gr = lid >> 2;
        const int qc = lid & 3;
#pragma unroll
        for (int mt = 0; mt < 2; mt++) {
#pragma unroll
            for (int hi = 0; hi < 2; hi++) {
                int co_l = mh * 32 + mt * 16 + hi * 8 + gr;
                float bb = bias[m0 + co_l];
                unsigned trow = base + (unsigned)co_l * 528u;
#pragma unroll
                for (int nn = 0; nn < 4; nn++) {
#pragma unroll
                    for (int lo = 0; lo < 2; lo++) {
                        int px = nq * 32 + nn * 8 + qc * 2 + lo;
                        float v = acc[mt][nn][hi * 2 + lo] + bb;
                        v = v > 0.f ? v : 0.f;
                        STS32(trow + (unsigned)px * 4u, __float_as_uint(v));
                    }
                }
            }
        }
    }
    __syncthreads();

    // coalesced write-out: g_h[b][m0+co][y0 + px/64][px%64]
    for (int idx = tid; idx < 4096; idx += 512) {
        int co = idx >> 5;
        int p4 = (idx & 31) * 4;
        unsigned a0, a1, a2, a3;
        asm volatile("ld.shared.v4.b32 {%0,%1,%2,%3}, [%4];"
                     : "=r"(a0), "=r"(a1), "=r"(a2), "=r"(a3)
                     : "r"(base + (unsigned)co * 528u + (unsigned)p4 * 4u));
        float* dst = g_h + (((size_t)b * 512 + m0 + co) * 64 + y0 + (p4 >> 6)) * 64
                     + (p4 & 63);
        *(float4*)dst = make_float4(__uint_as_float(a0), __uint_as_float(a1),
                                    __uint_as_float(a2), __uint_as_float(a3));
    }
}

// ---------------------------------------------------------------------------
// 1x1 heads + softmax fg + box decode + sort keys + score-bucket histogram
// ---------------------------------------------------------------------------
__global__ __launch_bounds__(128) void heads_kernel(
    const float* __restrict__ sw, const float* __restrict__ sb,
    const float* __restrict__ lw, const float* __restrict__ lb,
    float* __restrict__ out)
{
    __shared__ float ws[64 * 54];
    const int tid = threadIdx.x;
    const int pg  = blockIdx.x * 128 + tid;
    const int b   = pg >> 12;
    const int pix = pg & 4095;

    float acc[54];
#pragma unroll
    for (int c = 0; c < 54; c++) acc[c] = 0.f;

    for (int cc = 0; cc < 512; cc += 64) {
        for (int idx = tid; idx < 64 * 54; idx += 128) {
            int ci = idx / 54;
            int c  = idx - ci * 54;
            ws[idx] = (c < 18) ? sw[c * 512 + cc + ci]
                               : lw[(c - 18) * 512 + cc + ci];
        }
        __syncthreads();
#pragma unroll 4
        for (int ci = 0; ci < 64; ci++) {
            float v = g_h[((size_t)(b * 512 + cc + ci)) * 4096 + pix];
#pragma unroll
            for (int c = 0; c < 54; c++) acc[c] += v * ws[ci * 54 + c];
        }
        __syncthreads();
    }

    const int y  = pix >> 6;
    const int xq = pix & 63;
    const float sy = (float)(y * 16);
    const float sx = (float)(xq * 16);

#pragma unroll
    for (int k = 0; k < 9; k++) {
        const double RR[3] = {0.5, 1.0, 2.0};
        const double SS[3] = {8.0, 16.0, 32.0};
        double rr = RR[k / 3], ss = SS[k % 3];
        double hh = 16.0 * ss * sqrt(rr);
        double wd = 16.0 * ss * sqrt(1.0 / rr);
        float by1 = (float)(8.0 - hh * 0.5), bx1 = (float)(8.0 - wd * 0.5);
        float by2 = (float)(8.0 + hh * 0.5), bx2 = (float)(8.0 + wd * 0.5);
        float ay1 = sy + by1, ax1 = sx + bx1, ay2 = sy + by2, ax2 = sx + bx2;

        const int a = pix * 9 + k;
        if (b == 0) {
            float* ap = out + OFS_ANCH + (size_t)a * 4;
            ap[0] = ay1; ap[1] = ax1; ap[2] = ay2; ap[3] = ax2;
        }

        float s0 = acc[k * 2 + 0] + sb[k * 2 + 0];
        float s1 = acc[k * 2 + 1] + sb[k * 2 + 1];
        out[OFS_SCORES + (size_t)b * 73728 + (size_t)a * 2 + 0] = s0;
        out[OFS_SCORES + (size_t)b * 73728 + (size_t)a * 2 + 1] = s1;

        float d0 = acc[18 + k * 4 + 0] + lb[k * 4 + 0];
        float d1 = acc[18 + k * 4 + 1] + lb[k * 4 + 1];
        float d2 = acc[18 + k * 4 + 2] + lb[k * 4 + 2];
        float d3 = acc[18 + k * 4 + 3] + lb[k * 4 + 3];
        float* lp = out + OFS_LOCS + (size_t)b * 147456 + (size_t)a * 4;
        lp[0] = d0; lp[1] = d1; lp[2] = d2; lp[3] = d3;

        float ah = ay2 - ay1, aw = ax2 - ax1;
        float cy = ay1 + 0.5f * ah, cx = ax1 + 0.5f * aw;
        float cty = d0 * ah + cy, ctx = d1 * aw + cx;
        float th = expf(d2) * ah, tw = expf(d3) * aw;
        float cy1 = fminf(fmaxf(cty - 0.5f * th, 0.f), 1024.f);
        float cy2 = fminf(fmaxf(cty + 0.5f * th, 0.f), 1024.f);
        float cx1 = fminf(fmaxf(ctx - 0.5f * tw, 0.f), 1024.f);
        float cx2 = fminf(fmaxf(ctx + 0.5f * tw, 0.f), 1024.f);
        bool valid = (cy2 - cy1 >= 16.f) && (cx2 - cx1 >= 16.f);

        float m = fmaxf(s0, s1);
        float e0 = expf(s0 - m), e1 = expf(s1 - m);
        float p1 = e1 / (e0 + e1);

        g_boxes4[(size_t)b * A_TOTAL + a] = make_float4(cy1, cx1, cy2, cx2);

        unsigned long long key;
        if (valid) {
            unsigned u = __float_as_uint(p1);
            u = (u & 0x80000000u) ? ~u : (u | 0x80000000u);
            key = ((unsigned long long)(~u) << 32) | (unsigned)a;
        } else {
            key = (0xFF800000ull << 32) | (unsigned)a;  // -inf score
        }
        g_keys[(size_t)b * A_TOTAL + a] = key;
        atomicAdd(&g_hist[b * 65536 + (unsigned)(key >> 48)], 1u);
    }
}

// find bucket threshold covering rank NIN; also reset count + pad sel buffer
__global__ __launch_bounds__(1024) void select_kernel()
{
    const int b = blockIdx.x, tid = threadIdx.x;
    __shared__ int part[1024];
    const unsigned* h = g_hist + b * 65536;
    int s = 0;
    for (int k = 0; k < 64; k++) s += (int)h[tid * 64 + k];
    part[tid] = s;
    __syncthreads();
    for (int off = 1; off < 1024; off <<= 1) {
        int v = (tid >= off) ? part[tid - off] : 0;
        __syncthreads();
        part[tid] += v;
        __syncthreads();
    }
    int incl = part[tid];
    int excl = incl - s;
    if (excl < NIN && incl >= NIN) {
        int c = excl, T = tid * 64 + 63;
        for (int k = 0; k < 64; k++) {
            c += (int)h[tid * 64 + k];
            if (c >= NIN) { T = tid * 64 + k; break; }
        }
        g_thr[b] = T;
    }
    if (tid == 0) g_cnt[b] = 0;
    for (int i = tid; i < NSEL; i += 1024) g_sel[b * NSEL + i] = ~0ull;
}

__global__ void compact_sel_kernel()
{
    int i = blockIdx.x * 256 + threadIdx.x;
    int b = blockIdx.y;
    if (i >= A_TOTAL) return;
    unsigned long long key = g_keys[(size_t)b * A_TOTAL + i];
    if ((int)(unsigned)(key >> 48) <= g_thr[b]) {
        int p = atomicAdd(&g_cnt[b], 1);
        if (p < NSEL) g_sel[b * NSEL + p] = key;
    }
}

// per-batch smem bitonic sort of <=16384 selected keys, then gather top-6000
__global__ __launch_bounds__(1024) void sortsel_kernel()
{
    const int b = blockIdx.x, tid = threadIdx.x;
    extern __shared__ unsigned long long s[];
    for (int i = tid; i < NSEL; i += 1024) s[i] = g_sel[b * NSEL + i];
    __syncthreads();
    for (int k = 2; k <= NSEL; k <<= 1) {
        for (int j = k >> 1; j > 0; j >>= 1) {
            for (int t = tid; t < NSEL; t += 1024) {
                int ixj = t ^ j;
                if (ixj > t) {
                    unsigned long long A = s[t], B = s[ixj];
                    bool up = ((t & k) == 0);
                    if ((A > B) == up) { s[t] = B; s[ixj] = A; }
                }
            }
            __syncthreads();
        }
    }
    for (int i = tid; i < NIN; i += 1024) {
        unsigned long long key = s[i];
        unsigned idx = (unsigned)key;
        float4 bx = g_boxes4[(size_t)b * A_TOTAL + idx];
        g_bsort4[b * NIN + i] = bx;
        g_areas[b * NIN + i] = (bx.z - bx.x) * (bx.w - bx.y);
        g_keep[b * NIN + i] = (int)((key >> 63) == 0);
    }
}

// sequential greedy NMS, all-smem + register-resident owned boxes
__global__ __launch_bounds__(1024) void nms_kernel()
{
    const int b = blockIdx.x, tid = threadIdx.x;
    extern __shared__ char nsm[];
    float4* bsh = (float4*)nsm;                          // 96000 B
    float* ash = (float*)(nsm + 96000);                  // 24000 B
    unsigned char* ksh = (unsigned char*)(nsm + 120000); // 6000 B

    for (int i = tid; i < NIN; i += 1024) {
        bsh[i] = g_bsort4[b * NIN + i];
        ash[i] = g_areas[b * NIN + i];
        ksh[i] = (unsigned char)g_keep[b * NIN + i];
    }
    __syncthreads();

    float4 myb[6]; float mya[6]; int myk[6];
#pragma unroll
    for (int e = 0; e < 6; e++) {
        int j = tid * 6 + e;
        if (j < NIN) { myb[e] = bsh[j]; mya[e] = ash[j]; myk[e] = (int)ksh[j]; }
        else myk[e] = 0;
    }

    for (int i = 0; i < NIN - 1; i++) {
        if (ksh[i]) {
            float4 bi = bsh[i];
            float ai = ash[i];
#pragma unroll
            for (int e = 0; e < 6; e++) {
                int j = tid * 6 + e;
                if (myk[e] && j > i) {
                    float yy1 = fmaxf(bi.x, myb[e].x);
                    float xx1 = fmaxf(bi.y, myb[e].y);
                    float yy2 = fminf(bi.z, myb[e].z);
                    float xx2 = fminf(bi.w, myb[e].w);
                    float inter = fmaxf(yy2 - yy1, 0.f) * fmaxf(xx2 - xx1, 0.f);
                    float iou = inter / (ai + mya[e] - inter + 1e-9f);
                    if (iou > 0.7f) { myk[e] = 0; ksh[j] = 0; }
                }
            }
            __syncthreads();
        }
    }
    for (int i = tid; i < NIN; i += 1024) g_keep[b * NIN + i] = (int)ksh[i];
}

// compact kept boxes into first 300 rows; zero-fill the rest; roi_indices
__global__ __launch_bounds__(1024) void compact_kernel(float* __restrict__ out)
{
    const int b = blockIdx.x;
    const int tid = threadIdx.x;
    __shared__ int csum[1024];

    const int base = tid * 6;
    int local[6];
    int cnt = 0;
#pragma unroll
    for (int e = 0; e < 6; e++) {
        int i = base + e;
        int k = (i < NIN) ? g_keep[b * NIN + i] : 0;
        local[e] = k;
        cnt += k;
    }
    csum[tid] = cnt;
    __syncthreads();
    for (int off = 1; off < 1024; off <<= 1) {
        int v = (tid >= off) ? csum[tid - off] : 0;
        __syncthreads();
        csum[tid] += v;
        __syncthreads();
    }
    int rank = csum[tid] - cnt;

    float* rois = out + OFS_ROIS + (size_t)b * 1200;
    for (int i = tid; i < 1200; i += 1024) rois[i] = 0.f;
    float* ridx = out + OFS_RIDX + (size_t)b * 300;
    for (int i = tid; i < 300; i += 1024) ridx[i] = (float)b;
    __syncthreads();

    int r = rank;
#pragma unroll
    for (int e = 0; e < 6; e++) {
        int i = base + e;
        if (i < NIN && local[e]) {
            if (r < NOUTB) {
                float4 bx = g_bsort4[b * NIN + i];
                rois[r * 4 + 0] = bx.x;
                rois[r * 4 + 1] = bx.y;
                rois[r * 4 + 2] = bx.z;
                rois[r * 4 + 3] = bx.w;
            }
            r++;
        }
    }
}

extern "C" void kernel_launch(void* const* d_in, const int* in_sizes, int n_in,
                              void* d_out, int out_size)
{
    const float* x       = (const float*)d_in[0];
    const float* conv_w  = (const float*)d_in[1];
    const float* conv_b  = (const float*)d_in[2];
    const float* score_w = (const float*)d_in[3];
    const float* score_b = (const float*)d_in[4];
    const float* loc_w   = (const float*)d_in[5];
    const float* loc_b   = (const float*)d_in[6];
    float* out = (float*)d_out;

    const int CONV_SMEM = 1024 + 2 * 98304;   // align slack + 2 buffer sets
    cudaFuncSetAttribute(conv_mma_kernel,
        cudaFuncAttributeMaxDynamicSharedMemorySize, CONV_SMEM);
    cudaFuncSetAttribute(sortsel_kernel,
        cudaFuncAttributeMaxDynamicSharedMemorySize, NSEL * 8);
    cudaFuncSetAttribute(nms_kernel,
        cudaFuncAttributeMaxDynamicSharedMemorySize, 126016);

    wsplit_kernel<<<4608, 256>>>(conv_w);
    xsplit_kernel<<<8192, 256>>>(x);
    zerohist_kernel<<<256, 1024>>>();
    conv_mma_kernel<<<dim3(4, 128), 512, CONV_SMEM>>>(x, conv_b);
    heads_kernel<<<128, 128>>>(score_w, score_b, loc_w, loc_b, out);
    select_kernel<<<BATCH, 1024>>>();
    compact_sel_kernel<<<dim3(144, BATCH), 256>>>();
    sortsel_kernel<<<BATCH, 1024, NSEL * 8>>>();
    nms_kernel<<<BATCH, 1024, 126016>>>();
    compact_kernel<<<BATCH, 1024>>>(out);
}

// round 14
// speedup vs baseline: 3.6649x; 2.1539x over previous
#include <cuda_runtime.h>
#include <cuda_bf16.h>
#include <math.h>

#define A_TOTAL 36864
#define NIN     6000
#define NOUTB   300
#define BATCH   4
#define NSEL    16384
#define NWORDS  94

// output layout (float32, concatenated reference tuple)
#define OFS_SCORES 0
#define OFS_LOCS   294912
#define OFS_ROIS   884736
#define OFS_RIDX   889536
#define OFS_ANCH   890736

#define TSTRIDE (9u * 8u * 512u * 32u)   // u32 elements per split-term plane

// scratch (device globals; no allocation allowed)
__device__ float  g_h[BATCH * 512 * 4096];
__device__ unsigned g_wsplit[3 * 9 * 8 * 512 * 32];   // [term][kk][cic][co][j2] bf16x2
__device__ unsigned short g_xs0[BATCH * 4096 * 512];  // channel-last bf16 term planes
__device__ unsigned short g_xs1[BATCH * 4096 * 512];
__device__ unsigned short g_xs2[BATCH * 4096 * 512];
__device__ float4 g_boxes4[BATCH * A_TOTAL];
__device__ unsigned long long g_keys[BATCH * A_TOTAL];
__device__ unsigned g_hist[BATCH * 65536];
__device__ int    g_thr[BATCH];
__device__ int    g_cnt[BATCH];
__device__ unsigned long long g_sel[BATCH * NSEL];
__device__ float4 g_bsort4[BATCH * NIN];
__device__ float  g_areas[BATCH * NIN];
__device__ int    g_keep[BATCH * NIN];
__device__ unsigned long long g_nmsmask[(size_t)BATCH * NIN * NWORDS];

// ---------------------------------------------------------------------------
// helpers
// ---------------------------------------------------------------------------
#define SWZ(o) ((o) ^ (((o) >> 3) & 0x70))

static __device__ __forceinline__ unsigned smem_u32(const void* p) {
    unsigned a;
    asm("{ .reg .u64 t; cvta.to.shared.u64 t, %1; cvt.u32.u64 %0, t; }"
        : "=r"(a) : "l"(p));
    return a;
}
// no "memory" clobber — __syncthreads() is the fence
#define STS32(addr, val) \
    asm volatile("st.shared.b32 [%0], %1;" :: "r"(addr), "r"(val))

#define LDS64(d, a) \
    asm volatile("ld.shared.b64 %0, [%1];" : "=l"(d) : "r"(a))

#define CP8(dst, src) \
    asm volatile("cp.async.ca.shared.global [%0], [%1], 8;" \
                 :: "r"(dst), "l"(src))
#define CP16(dst, src) \
    asm volatile("cp.async.cg.shared.global [%0], [%1], 16;" \
                 :: "r"(dst), "l"(src))
#define CP16Z(dst, src, sz) \
    asm volatile("cp.async.cg.shared.global [%0], [%1], 16, %2;" \
                 :: "r"(dst), "l"(src), "r"(sz))
#define CP_COMMIT() asm volatile("cp.async.commit_group;")
#define CP_WAIT0()  asm volatile("cp.async.wait_group 0;")

#define LDSM_X4(r0, r1, r2, r3, addr) \
    asm volatile("ldmatrix.sync.aligned.m8n8.x4.shared.b16 {%0,%1,%2,%3}, [%4];" \
                 : "=r"(r0), "=r"(r1), "=r"(r2), "=r"(r3) : "r"(addr))

#define MMA16816(d0, d1, d2, d3, a0, a1, a2, a3, b0, b1) \
    asm volatile("mma.sync.aligned.m16n8k16.row.col.f32.bf16.bf16.f32 " \
                 "{%0,%1,%2,%3}, {%4,%5,%6,%7}, {%8,%9}, {%0,%1,%2,%3};" \
                 : "+f"(d0), "+f"(d1), "+f"(d2), "+f"(d3) \
                 : "r"(a0), "r"(a1), "r"(a2), "r"(a3), "r"(b0), "r"(b1))

static __device__ __forceinline__ void split3(float v, unsigned short o[3]) {
    __nv_bfloat16 b0 = __float2bfloat16_rn(v);
    float f0 = __bfloat162float(b0);
    float r1 = v - f0;
    __nv_bfloat16 b1 = __float2bfloat16_rn(r1);
    float f1 = __bfloat162float(b1);
    __nv_bfloat16 b2 = __float2bfloat16_rn(r1 - f1);
    o[0] = __bfloat16_as_ushort(b0);
    o[1] = __bfloat16_as_ushort(b1);
    o[2] = __bfloat16_as_ushort(b2);
}

// ---------------------------------------------------------------------------
// weight split precompute: w[co][ci][kk] -> 3 bf16 planes [kk][cic][co][j2]
// ---------------------------------------------------------------------------
__global__ void wsplit_kernel(const float* __restrict__ w)
{
    int idx = blockIdx.x * 256 + threadIdx.x;   // 9*8*512*32 = 1,179,648 exact
    int j2  = idx & 31;
    int co  = (idx >> 5) & 511;
    int cic = (idx >> 14) & 7;
    int kk  = idx >> 17;
    if (kk >= 9) return;
    int ci = cic * 64 + j2 * 2;
    float v0 = w[((size_t)co * 512 + ci) * 9 + kk];
    float v1 = w[((size_t)co * 512 + ci + 1) * 9 + kk];
    unsigned short h[3], g[3];
    split3(v0, h);
    split3(v1, g);
    unsigned base = (((unsigned)kk * 8 + cic) * 512 + co) * 32 + j2;
#pragma unroll
    for (int t = 0; t < 3; t++)
        g_wsplit[t * TSTRIDE + base] = (unsigned)h[t] | ((unsigned)g[t] << 16);
}

// ---------------------------------------------------------------------------
// input split precompute: x[b][ci][y][x] f32 -> channel-last bf16 planes
// ---------------------------------------------------------------------------
__global__ __launch_bounds__(256) void xsplit_kernel(const float* __restrict__ x)
{
    __shared__ float t[32][33];
    const int bid = blockIdx.x;          // 4 * 16 * 128 = 8192 blocks
    const int pt  = bid & 127;           // pixel tile (32 px)
    const int ct  = (bid >> 7) & 15;     // ci tile (32 ci)
    const int b   = bid >> 11;
    const int tid = threadIdx.x;

    const float* xp = x + ((size_t)b * 512 + ct * 32) * 4096 + pt * 32;
#pragma unroll
    for (int k = 0; k < 4; k++) {
        int l = tid + k * 256;
        int ci_l = l >> 5, px_l = l & 31;
        t[ci_l][px_l] = xp[(size_t)ci_l * 4096 + px_l];
    }
    __syncthreads();
#pragma unroll
    for (int k = 0; k < 4; k++) {
        int l = tid + k * 256;
        int px_l = l >> 5, ci_l = l & 31;
        float v = t[ci_l][px_l];
        unsigned short h[3];
        split3(v, h);
        size_t o = ((size_t)b * 4096 + pt * 32 + px_l) * 512 + ct * 32 + ci_l;
        g_xs0[o] = h[0];
        g_xs1[o] = h[1];
        g_xs2[o] = h[2];
    }
}

__global__ void zerohist_kernel()
{
    g_hist[blockIdx.x * 1024 + threadIdx.x] = 0u;
}

// ---------------------------------------------------------------------------
// 3x3 conv 512->512 + bias + relu via mma.sync bf16 6-term emulated-fp32.
// (unchanged from R13)
// ---------------------------------------------------------------------------
__global__ __launch_bounds__(512, 1) void conv_mma_kernel(
    const float* __restrict__ x, const float* __restrict__ bias)
{
    extern __shared__ __align__(16) char dsm[];
    const unsigned raw  = smem_u32(dsm);
    const unsigned base = (raw + 1023u) & ~1023u;  // 1024-aligned tiles

    const int tid = threadIdx.x;
    const int wid = tid >> 5;
    const int lid = tid & 31;
    const int m0  = blockIdx.x * 128;
    const int b   = blockIdx.y >> 5;
    const int y0  = (blockIdx.y & 31) * 2;

    const int mh = wid >> 2;            // co block of 32 (0..3)
    const int nq = wid & 3;             // px block of 32 (0..3)
    const int rlow = lid & 15;
    const int chalf = (lid >> 4) * 16;

    float acc[2][4][4];
    float P[2][4][4];
#pragma unroll
    for (int i = 0; i < 2; i++)
#pragma unroll
        for (int j = 0; j < 4; j++)
#pragma unroll
            for (int r = 0; r < 4; r++) { acc[i][j][r] = 0.f; P[i][j][r] = 0.f; }

    auto stageAB = [&](int c, int s) {
        const int kk  = c >> 3;
        const int cic = c & 7;
        const int dy  = kk / 3, dx = kk - dy * 3;
        const int ci0 = cic * 64;
        const unsigned sb = base + (unsigned)s * 98304u;
        const unsigned* wp = g_wsplit + ((unsigned)(kk * 8 + cic) * 512 + m0) * 32;
#pragma unroll
        for (int it = 0; it < 2; it++) {
            int idx = tid + it * 512;
            int co = idx >> 3, seg = idx & 7;
            unsigned off = SWZ((unsigned)(co * 128 + seg * 16));
            const unsigned* sp = wp + co * 32 + seg * 4;
            CP16(sb + 49152u + off, sp);
            CP16(sb + 65536u + off, sp + TSTRIDE);
            CP16(sb + 81920u + off, sp + 2 * TSTRIDE);
        }
#pragma unroll
        for (int it = 0; it < 2; it++) {
            int idx = tid + it * 512;
            int px = idx >> 3, seg = idx & 7;
            int yy = y0 + (px >> 6) + dy - 1;
            int xx = (px & 63) + dx - 1;
            bool ok = ((unsigned)yy < 64u) && ((unsigned)xx < 64u);
            int yc = ok ? yy : 0, xc = ok ? xx : 0;
            size_t po = ((size_t)b * 4096 + (size_t)yc * 64 + xc) * 512
                        + ci0 + seg * 8;
            unsigned off = SWZ((unsigned)(px * 128 + seg * 16));
            int sz = ok ? 16 : 0;
            CP16Z(sb + off,          g_xs0 + po, sz);
            CP16Z(sb + 16384u + off, g_xs1 + po, sz);
            CP16Z(sb + 32768u + off, g_xs2 + po, sz);
        }
    };

    auto k16step = [&](unsigned Ab, unsigned Bb, int ks) {
        unsigned bf[2][4], af[2][4];
#pragma unroll
        for (int bn = 0; bn < 2; bn++) {
            unsigned baddr = Bb +
                SWZ((unsigned)((nq * 32 + bn * 16 + rlow) * 128 + ks * 32 + chalf));
            LDSM_X4(bf[bn][0], bf[bn][1], bf[bn][2], bf[bn][3], baddr);
        }
#pragma unroll
        for (int mt = 0; mt < 2; mt++) {
            unsigned aaddr = Ab +
                SWZ((unsigned)((mh * 32 + mt * 16 + rlow) * 128 + ks * 32 + chalf));
            LDSM_X4(af[mt][0], af[mt][1], af[mt][2], af[mt][3], aaddr);
        }
#pragma unroll
        for (int mt = 0; mt < 2; mt++)
#pragma unroll
            for (int bn = 0; bn < 2; bn++) {
                MMA16816(P[mt][bn*2][0], P[mt][bn*2][1], P[mt][bn*2][2], P[mt][bn*2][3],
                         af[mt][0], af[mt][1], af[mt][2], af[mt][3],
                         bf[bn][0], bf[bn][2]);
                MMA16816(P[mt][bn*2+1][0], P[mt][bn*2+1][1], P[mt][bn*2+1][2], P[mt][bn*2+1][3],
                         af[mt][0], af[mt][1], af[mt][2], af[mt][3],
                         bf[bn][1], bf[bn][3]);
            }
    };

    auto drain = [&]() {
#pragma unroll
        for (int i = 0; i < 2; i++)
#pragma unroll
            for (int j = 0; j < 4; j++)
#pragma unroll
                for (int r = 0; r < 4; r++) { acc[i][j][r] += P[i][j][r]; P[i][j][r] = 0.f; }
    };

    stageAB(0, 0);
    CP_COMMIT();
    CP_WAIT0();
    __syncthreads();

    for (int c = 0; c < 72; c++) {
        const int s = c & 1;
        if (c + 1 < 72) {
            stageAB(c + 1, s ^ 1);
            CP_COMMIT();
        }

        const unsigned sb = base + (unsigned)s * 98304u;
#pragma unroll
        for (int ks = 0; ks < 4; ks++)
            k16step(sb + 49152u, sb, ks);
        drain();
        const int TA[5] = {0, 1, 1, 0, 2};
        const int TB[5] = {1, 0, 1, 2, 0};
#pragma unroll
        for (int t = 0; t < 5; t++) {
            const unsigned Ab = sb + 49152u + (unsigned)TA[t] * 16384u;
            const unsigned Bb = sb + (unsigned)TB[t] * 16384u;
#pragma unroll
            for (int ks = 0; ks < 4; ks++)
                k16step(Ab, Bb, ks);
        }
        drain();

        if (c + 1 < 72) CP_WAIT0();
        __syncthreads();
    }

    {
        const int gr = lid >> 2;
        const int qc = lid & 3;
#pragma unroll
        for (int mt = 0; mt < 2; mt++) {
#pragma unroll
            for (int hi = 0; hi < 2; hi++) {
                int co_l = mh * 32 + mt * 16 + hi * 8 + gr;
                float bb = bias[m0 + co_l];
                unsigned trow = base + (unsigned)co_l * 528u;
#pragma unroll
                for (int nn = 0; nn < 4; nn++) {
#pragma unroll
                    for (int lo = 0; lo < 2; lo++) {
                        int px = nq * 32 + nn * 8 + qc * 2 + lo;
                        float v = acc[mt][nn][hi * 2 + lo] + bb;
                        v = v > 0.f ? v : 0.f;
                        STS32(trow + (unsigned)px * 4u, __float_as_uint(v));
                    }
                }
            }
        }
    }
    __syncthreads();

    for (int idx = tid; idx < 4096; idx += 512) {
        int co = idx >> 5;
        int p4 = (idx & 31) * 4;
        unsigned a0, a1, a2, a3;
        asm volatile("ld.shared.v4.b32 {%0,%1,%2,%3}, [%4];"
                     : "=r"(a0), "=r"(a1), "=r"(a2), "=r"(a3)
                     : "r"(base + (unsigned)co * 528u + (unsigned)p4 * 4u));
        float* dst = g_h + (((size_t)b * 512 + m0 + co) * 64 + y0 + (p4 >> 6)) * 64
                     + (p4 & 63);
        *(float4*)dst = make_float4(__uint_as_float(a0), __uint_as_float(a1),
                                    __uint_as_float(a2), __uint_as_float(a3));
    }
}

// ---------------------------------------------------------------------------
// 1x1 heads + softmax fg + box decode + sort keys + score-bucket histogram
// ---------------------------------------------------------------------------
__global__ __launch_bounds__(128) void heads_kernel(
    const float* __restrict__ sw, const float* __restrict__ sb,
    const float* __restrict__ lw, const float* __restrict__ lb,
    float* __restrict__ out)
{
    __shared__ float ws[64 * 54];
    const int tid = threadIdx.x;
    const int pg  = blockIdx.x * 128 + tid;
    const int b   = pg >> 12;
    const int pix = pg & 4095;

    float acc[54];
#pragma unroll
    for (int c = 0; c < 54; c++) acc[c] = 0.f;

    for (int cc = 0; cc < 512; cc += 64) {
        for (int idx = tid; idx < 64 * 54; idx += 128) {
            int ci = idx / 54;
            int c  = idx - ci * 54;
            ws[idx] = (c < 18) ? sw[c * 512 + cc + ci]
                               : lw[(c - 18) * 512 + cc + ci];
        }
        __syncthreads();
#pragma unroll 4
        for (int ci = 0; ci < 64; ci++) {
            float v = g_h[((size_t)(b * 512 + cc + ci)) * 4096 + pix];
#pragma unroll
            for (int c = 0; c < 54; c++) acc[c] += v * ws[ci * 54 + c];
        }
        __syncthreads();
    }

    const int y  = pix >> 6;
    const int xq = pix & 63;
    const float sy = (float)(y * 16);
    const float sx = (float)(xq * 16);

#pragma unroll
    for (int k = 0; k < 9; k++) {
        const double RR[3] = {0.5, 1.0, 2.0};
        const double SS[3] = {8.0, 16.0, 32.0};
        double rr = RR[k / 3], ss = SS[k % 3];
        double hh = 16.0 * ss * sqrt(rr);
        double wd = 16.0 * ss * sqrt(1.0 / rr);
        float by1 = (float)(8.0 - hh * 0.5), bx1 = (float)(8.0 - wd * 0.5);
        float by2 = (float)(8.0 + hh * 0.5), bx2 = (float)(8.0 + wd * 0.5);
        float ay1 = sy + by1, ax1 = sx + bx1, ay2 = sy + by2, ax2 = sx + bx2;

        const int a = pix * 9 + k;
        if (b == 0) {
            float* ap = out + OFS_ANCH + (size_t)a * 4;
            ap[0] = ay1; ap[1] = ax1; ap[2] = ay2; ap[3] = ax2;
        }

        float s0 = acc[k * 2 + 0] + sb[k * 2 + 0];
        float s1 = acc[k * 2 + 1] + sb[k * 2 + 1];
        out[OFS_SCORES + (size_t)b * 73728 + (size_t)a * 2 + 0] = s0;
        out[OFS_SCORES + (size_t)b * 73728 + (size_t)a * 2 + 1] = s1;

        float d0 = acc[18 + k * 4 + 0] + lb[k * 4 + 0];
        float d1 = acc[18 + k * 4 + 1] + lb[k * 4 + 1];
        float d2 = acc[18 + k * 4 + 2] + lb[k * 4 + 2];
        float d3 = acc[18 + k * 4 + 3] + lb[k * 4 + 3];
        float* lp = out + OFS_LOCS + (size_t)b * 147456 + (size_t)a * 4;
        lp[0] = d0; lp[1] = d1; lp[2] = d2; lp[3] = d3;

        float ah = ay2 - ay1, aw = ax2 - ax1;
        float cy = ay1 + 0.5f * ah, cx = ax1 + 0.5f * aw;
        float cty = d0 * ah + cy, ctx = d1 * aw + cx;
        float th = expf(d2) * ah, tw = expf(d3) * aw;
        float cy1 = fminf(fmaxf(cty - 0.5f * th, 0.f), 1024.f);
        float cy2 = fminf(fmaxf(cty + 0.5f * th, 0.f), 1024.f);
        float cx1 = fminf(fmaxf(ctx - 0.5f * tw, 0.f), 1024.f);
        float cx2 = fminf(fmaxf(ctx + 0.5f * tw, 0.f), 1024.f);
        bool valid = (cy2 - cy1 >= 16.f) && (cx2 - cx1 >= 16.f);

        float m = fmaxf(s0, s1);
        float e0 = expf(s0 - m), e1 = expf(s1 - m);
        float p1 = e1 / (e0 + e1);

        g_boxes4[(size_t)b * A_TOTAL + a] = make_float4(cy1, cx1, cy2, cx2);

        unsigned long long key;
        if (valid) {
            unsigned u = __float_as_uint(p1);
            u = (u & 0x80000000u) ? ~u : (u | 0x80000000u);
            key = ((unsigned long long)(~u) << 32) | (unsigned)a;
        } else {
            key = (0xFF800000ull << 32) | (unsigned)a;  // -inf score
        }
        g_keys[(size_t)b * A_TOTAL + a] = key;
        atomicAdd(&g_hist[b * 65536 + (unsigned)(key >> 48)], 1u);
    }
}

// find bucket threshold covering rank NIN; also reset count + pad sel buffer
__global__ __launch_bounds__(1024) void select_kernel()
{
    const int b = blockIdx.x, tid = threadIdx.x;
    __shared__ int part[1024];
    const unsigned* h = g_hist + b * 65536;
    int s = 0;
    for (int k = 0; k < 64; k++) s += (int)h[tid * 64 + k];
    part[tid] = s;
    __syncthreads();
    for (int off = 1; off < 1024; off <<= 1) {
        int v = (tid >= off) ? part[tid - off] : 0;
        __syncthreads();
        part[tid] += v;
        __syncthreads();
    }
    int incl = part[tid];
    int excl = incl - s;
    if (excl < NIN && incl >= NIN) {
        int c = excl, T = tid * 64 + 63;
        for (int k = 0; k < 64; k++) {
            c += (int)h[tid * 64 + k];
            if (c >= NIN) { T = tid * 64 + k; break; }
        }
        g_thr[b] = T;
    }
    if (tid == 0) g_cnt[b] = 0;
    for (int i = tid; i < NSEL; i += 1024) g_sel[b * NSEL + i] = ~0ull;
}

__global__ void compact_sel_kernel()
{
    int i = blockIdx.x * 256 + threadIdx.x;
    int b = blockIdx.y;
    if (i >= A_TOTAL) return;
    unsigned long long key = g_keys[(size_t)b * A_TOTAL + i];
    if ((int)(unsigned)(key >> 48) <= g_thr[b]) {
        int p = atomicAdd(&g_cnt[b], 1);
        if (p < NSEL) g_sel[b * NSEL + p] = key;
    }
}

// per-batch smem bitonic sort of <=16384 selected keys, then gather top-6000
__global__ __launch_bounds__(1024) void sortsel_kernel()
{
    const int b = blockIdx.x, tid = threadIdx.x;
    extern __shared__ unsigned long long s[];
    for (int i = tid; i < NSEL; i += 1024) s[i] = g_sel[b * NSEL + i];
    __syncthreads();
    for (int k = 2; k <= NSEL; k <<= 1) {
        for (int j = k >> 1; j > 0; j >>= 1) {
            for (int t = tid; t < NSEL; t += 1024) {
                int ixj = t ^ j;
                if (ixj > t) {
                    unsigned long long A = s[t], B = s[ixj];
                    bool up = ((t & k) == 0);
                    if ((A > B) == up) { s[t] = B; s[ixj] = A; }
                }
            }
            __syncthreads();
        }
    }
    for (int i = tid; i < NIN; i += 1024) {
        unsigned long long key = s[i];
        unsigned idx = (unsigned)key;
        float4 bx = g_boxes4[(size_t)b * A_TOTAL + idx];
        g_bsort4[b * NIN + i] = bx;
        g_areas[b * NIN + i] = (bx.z - bx.x) * (bx.w - bx.y);
        g_keep[b * NIN + i] = (int)((key >> 63) == 0);
    }
}

// ---------------------------------------------------------------------------
// NMS stage 1 (parallel): suppression bitmask rows.
// One warp per sorted box i; lanes sweep j in 32-chunks; ballot -> bits.
// IoU expression identical to the previous sequential NMS.
// ---------------------------------------------------------------------------
__global__ __launch_bounds__(256) void nmsmask_kernel()
{
    const int b = blockIdx.y;
    const int i = blockIdx.x * 8 + (threadIdx.x >> 5);
    const int lane = threadIdx.x & 31;
    if (i >= NIN) return;
    const float4* bx = g_bsort4 + (size_t)b * NIN;
    const float*  ar = g_areas + b * NIN;
    float4 bi = bx[i];
    float  ai = ar[i];
    unsigned long long* row = g_nmsmask + ((size_t)b * NIN + i) * NWORDS;
    unsigned mlo = 0;
#pragma unroll 4
    for (int sc = 0; sc < 2 * NWORDS; sc++) {     // 188 subchunks of 32
        int j = sc * 32 + lane;
        bool sup = false;
        if (sc * 32 + 31 > i) {                   // subchunk contains j > i
            if (j > i && j < NIN) {
                float4 bj = bx[j];
                float yy1 = fmaxf(bi.x, bj.x);
                float xx1 = fmaxf(bi.y, bj.y);
                float yy2 = fminf(bi.z, bj.z);
                float xx2 = fminf(bi.w, bj.w);
                float inter = fmaxf(yy2 - yy1, 0.f) * fmaxf(xx2 - xx1, 0.f);
                float iou = inter / (ai + ar[j] - inter + 1e-9f);
                sup = iou > 0.7f;
            }
        }
        unsigned m = __ballot_sync(0xffffffffu, sup);
        if (sc & 1) {
            if (lane == 0)
                row[sc >> 1] = (unsigned long long)mlo
                             | ((unsigned long long)m << 32);
        } else {
            mlo = m;
        }
    }
}

// ---------------------------------------------------------------------------
// NMS stage 2 (serial, 1 warp per batch): greedy scan over register bitmap.
// Mask rows prefetched through a 16-deep cp.async smem ring.
// ---------------------------------------------------------------------------
__global__ __launch_bounds__(32) void nmsscan_kernel()
{
    __shared__ __align__(16) unsigned long long ring[16][96];
    const int b = blockIdx.x;
    const int lane = threadIdx.x;
    const unsigned long long* mask = g_nmsmask + (size_t)b * NIN * NWORDS;
    const int* kin = g_keep + b * NIN;

    const int w0 = lane, w1 = lane + 32, w2 = lane + 64;
    unsigned long long k0 = 0, k1 = 0, k2 = 0;
#pragma unroll 1
    for (int k = 0; k < 64; k++) {
        k0 |= (unsigned long long)(kin[w0 * 64 + k] & 1) << k;
        k1 |= (unsigned long long)(kin[w1 * 64 + k] & 1) << k;
        int j2 = w2 * 64 + k;
        if (w2 < NWORDS && j2 < NIN)
            k2 |= (unsigned long long)(kin[j2] & 1) << k;
    }

    const unsigned rbase = smem_u32(ring);
    auto issue = [&](int i) {
        unsigned dst = rbase + (unsigned)(i & 15) * 768u;
        const unsigned long long* src = mask + (size_t)i * NWORDS;
        CP8(dst + (unsigned)lane * 8u, src + lane);
        CP8(dst + (unsigned)(lane + 32) * 8u, src + lane + 32);
        if (lane < NWORDS - 64) CP8(dst + (unsigned)(lane + 64) * 8u, src + lane + 64);
        CP_COMMIT();
    };
    for (int i = 0; i < 15; i++) issue(i);

    unsigned long long cur = __shfl_sync(0xffffffffu, k0, 0);

    for (int i = 0; i < NIN; i++) {
        asm volatile("cp.async.wait_group 14;");
        if ((i & 63) == 0 && i) {
            int w = i >> 6;
            unsigned long long kw = (w < 32) ? k0 : ((w < 64) ? k1 : k2);
            cur = __shfl_sync(0xffffffffu, kw, w & 31);
        }
        bool alive = (cur >> (i & 63)) & 1ull;
        if (alive) {
            unsigned saddr = rbase + (unsigned)(i & 15) * 768u;
            unsigned long long r0, r1, r2 = 0;
            LDS64(r0, saddr + (unsigned)lane * 8u);
            LDS64(r1, saddr + (unsigned)(lane + 32) * 8u);
            if (lane < NWORDS - 64) LDS64(r2, saddr + (unsigned)(lane + 64) * 8u);
            k0 &= ~r0;
            k1 &= ~r1;
            k2 &= ~r2;
            int w = i >> 6;
            unsigned long long rw = (w < 32) ? r0 : ((w < 64) ? r1 : r2);
            rw = __shfl_sync(0xffffffffu, rw, w & 31);
            cur &= ~rw;
        }
        if (i + 15 < NIN) issue(i + 15);
    }

    int* kout = g_keep + b * NIN;
#pragma unroll 1
    for (int k = 0; k < 64; k++) {
        kout[w0 * 64 + k] = (int)((k0 >> k) & 1ull);
        kout[w1 * 64 + k] = (int)((k1 >> k) & 1ull);
        int j2 = w2 * 64 + k;
        if (w2 < NWORDS && j2 < NIN)
            kout[j2] = (int)((k2 >> k) & 1ull);
    }
}

// compact kept boxes into first 300 rows; zero-fill the rest; roi_indices
__global__ __launch_bounds__(1024) void compact_kernel(float* __restrict__ out)
{
    const int b = blockIdx.x;
    const int tid = threadIdx.x;
    __shared__ int csum[1024];

    const int base = tid * 6;
    int local[6];
    int cnt = 0;
#pragma unroll
    for (int e = 0; e < 6; e++) {
        int i = base + e;
        int k = (i < NIN) ? g_keep[b * NIN + i] : 0;
        local[e] = k;
        cnt += k;
    }
    csum[tid] = cnt;
    __syncthreads();
    for (int off = 1; off < 1024; off <<= 1) {
        int v = (tid >= off) ? csum[tid - off] : 0;
        __syncthreads();
        csum[tid] += v;
        __syncthreads();
    }
    int rank = csum[tid] - cnt;

    float* rois = out + OFS_ROIS + (size_t)b * 1200;
    for (int i = tid; i < 1200; i += 1024) rois[i] = 0.f;
    float* ridx = out + OFS_RIDX + (size_t)b * 300;
    for (int i = tid; i < 300; i += 1024) ridx[i] = (float)b;
    __syncthreads();

    int r = rank;
#pragma unroll
    for (int e = 0; e < 6; e++) {
        int i = base + e;
        if (i < NIN && local[e]) {
            if (r < NOUTB) {
                float4 bx = g_bsort4[b * NIN + i];
                rois[r * 4 + 0] = bx.x;
                rois[r * 4 + 1] = bx.y;
                rois[r * 4 + 2] = bx.z;
                rois[r * 4 + 3] = bx.w;
            }
            r++;
        }
    }
}

extern "C" void kernel_launch(void* const* d_in, const int* in_sizes, int n_in,
                              void* d_out, int out_size)
{
    const float* x       = (const float*)d_in[0];
    const float* conv_w  = (const float*)d_in[1];
    const float* conv_b  = (const float*)d_in[2];
    const float* score_w = (const float*)d_in[3];
    const float* score_b = (const float*)d_in[4];
    const float* loc_w   = (const float*)d_in[5];
    const float* loc_b   = (const float*)d_in[6];
    float* out = (float*)d_out;

    const int CONV_SMEM = 1024 + 2 * 98304;   // align slack + 2 buffer sets
    cudaFuncSetAttribute(conv_mma_kernel,
        cudaFuncAttributeMaxDynamicSharedMemorySize, CONV_SMEM);
    cudaFuncSetAttribute(sortsel_kernel,
        cudaFuncAttributeMaxDynamicSharedMemorySize, NSEL * 8);

    wsplit_kernel<<<4608, 256>>>(conv_w);
    xsplit_kernel<<<8192, 256>>>(x);
    zerohist_kernel<<<256, 1024>>>();
    conv_mma_kernel<<<dim3(4, 128), 512, CONV_SMEM>>>(x, conv_b);
    heads_kernel<<<128, 128>>>(score_w, score_b, loc_w, loc_b, out);
    select_kernel<<<BATCH, 1024>>>();
    compact_sel_kernel<<<dim3(144, BATCH), 256>>>();
    sortsel_kernel<<<BATCH, 1024, NSEL * 8>>>();
    nmsmask_kernel<<<dim3(750, BATCH), 256>>>();
    nmsscan_kernel<<<BATCH, 32>>>();
    compact_kernel<<<BATCH, 1024>>>(out);
}

// round 15
// speedup vs baseline: 5.3259x; 1.4532x over previous
#include <cuda_runtime.h>
#include <cuda_bf16.h>
#include <math.h>

#define A_TOTAL 36864
#define NIN     6000
#define NOUTB   300
#define BATCH   4
#define NSEL    16384
#define NWORDS  94

// output layout (float32, concatenated reference tuple)
#define OFS_SCORES 0
#define OFS_LOCS   294912
#define OFS_ROIS   884736
#define OFS_RIDX   889536
#define OFS_ANCH   890736

#define TSTRIDE (9u * 8u * 512u * 32u)   // u32 elements per split-term plane

// scratch (device globals; no allocation allowed)
__device__ float  g_h[BATCH * 512 * 4096];
__device__ unsigned g_wsplit[3 * 9 * 8 * 512 * 32];   // [term][kk][cic][co][j2] bf16x2
__device__ unsigned short g_xs0[BATCH * 4096 * 512];  // channel-last bf16 term planes
__device__ unsigned short g_xs1[BATCH * 4096 * 512];
__device__ unsigned short g_xs2[BATCH * 4096 * 512];
__device__ float4 g_boxes4[BATCH * A_TOTAL];
__device__ unsigned long long g_keys[BATCH * A_TOTAL];
__device__ unsigned g_hist[BATCH * 65536];
__device__ int    g_thr[BATCH];
__device__ int    g_cnt[BATCH];
__device__ unsigned long long g_sel[BATCH * NSEL];
__device__ float4 g_bsort4[BATCH * NIN];
__device__ float  g_areas[BATCH * NIN];
__device__ int    g_keep[BATCH * NIN];
__device__ unsigned long long g_nmsmask[(size_t)BATCH * NIN * NWORDS];

// ---------------------------------------------------------------------------
// helpers
// ---------------------------------------------------------------------------
#define SWZ(o) ((o) ^ (((o) >> 3) & 0x70))

static __device__ __forceinline__ unsigned smem_u32(const void* p) {
    unsigned a;
    asm("{ .reg .u64 t; cvta.to.shared.u64 t, %1; cvt.u32.u64 %0, t; }"
        : "=r"(a) : "l"(p));
    return a;
}
// no "memory" clobber — __syncthreads() is the fence
#define STS32(addr, val) \
    asm volatile("st.shared.b32 [%0], %1;" :: "r"(addr), "r"(val))

#define LDS64(d, a) \
    asm volatile("ld.shared.b64 %0, [%1];" : "=l"(d) : "r"(a))

#define CP8(dst, src) \
    asm volatile("cp.async.ca.shared.global [%0], [%1], 8;" \
                 :: "r"(dst), "l"(src))
#define CP16(dst, src) \
    asm volatile("cp.async.cg.shared.global [%0], [%1], 16;" \
                 :: "r"(dst), "l"(src))
#define CP16Z(dst, src, sz) \
    asm volatile("cp.async.cg.shared.global [%0], [%1], 16, %2;" \
                 :: "r"(dst), "l"(src), "r"(sz))
#define CP_COMMIT() asm volatile("cp.async.commit_group;")
#define CP_WAIT0()  asm volatile("cp.async.wait_group 0;")

#define LDSM_X4(r0, r1, r2, r3, addr) \
    asm volatile("ldmatrix.sync.aligned.m8n8.x4.shared.b16 {%0,%1,%2,%3}, [%4];" \
                 : "=r"(r0), "=r"(r1), "=r"(r2), "=r"(r3) : "r"(addr))

#define MMA16816(d0, d1, d2, d3, a0, a1, a2, a3, b0, b1) \
    asm volatile("mma.sync.aligned.m16n8k16.row.col.f32.bf16.bf16.f32 " \
                 "{%0,%1,%2,%3}, {%4,%5,%6,%7}, {%8,%9}, {%0,%1,%2,%3};" \
                 : "+f"(d0), "+f"(d1), "+f"(d2), "+f"(d3) \
                 : "r"(a0), "r"(a1), "r"(a2), "r"(a3), "r"(b0), "r"(b1))

static __device__ __forceinline__ void split3(float v, unsigned short o[3]) {
    __nv_bfloat16 b0 = __float2bfloat16_rn(v);
    float f0 = __bfloat162float(b0);
    float r1 = v - f0;
    __nv_bfloat16 b1 = __float2bfloat16_rn(r1);
    float f1 = __bfloat162float(b1);
    __nv_bfloat16 b2 = __float2bfloat16_rn(r1 - f1);
    o[0] = __bfloat16_as_ushort(b0);
    o[1] = __bfloat16_as_ushort(b1);
    o[2] = __bfloat16_as_ushort(b2);
}

// ---------------------------------------------------------------------------
// weight split precompute: w[co][ci][kk] -> 3 bf16 planes [kk][cic][co][j2]
// ---------------------------------------------------------------------------
__global__ void wsplit_kernel(const float* __restrict__ w)
{
    int idx = blockIdx.x * 256 + threadIdx.x;   // 9*8*512*32 = 1,179,648 exact
    int j2  = idx & 31;
    int co  = (idx >> 5) & 511;
    int cic = (idx >> 14) & 7;
    int kk  = idx >> 17;
    if (kk >= 9) return;
    int ci = cic * 64 + j2 * 2;
    float v0 = w[((size_t)co * 512 + ci) * 9 + kk];
    float v1 = w[((size_t)co * 512 + ci + 1) * 9 + kk];
    unsigned short h[3], g[3];
    split3(v0, h);
    split3(v1, g);
    unsigned base = (((unsigned)kk * 8 + cic) * 512 + co) * 32 + j2;
#pragma unroll
    for (int t = 0; t < 3; t++)
        g_wsplit[t * TSTRIDE + base] = (unsigned)h[t] | ((unsigned)g[t] << 16);
}

// ---------------------------------------------------------------------------
// input split precompute: x[b][ci][y][x] f32 -> channel-last bf16 planes
// ---------------------------------------------------------------------------
__global__ __launch_bounds__(256) void xsplit_kernel(const float* __restrict__ x)
{
    __shared__ float t[32][33];
    const int bid = blockIdx.x;          // 4 * 16 * 128 = 8192 blocks
    const int pt  = bid & 127;           // pixel tile (32 px)
    const int ct  = (bid >> 7) & 15;     // ci tile (32 ci)
    const int b   = bid >> 11;
    const int tid = threadIdx.x;

    const float* xp = x + ((size_t)b * 512 + ct * 32) * 4096 + pt * 32;
#pragma unroll
    for (int k = 0; k < 4; k++) {
        int l = tid + k * 256;
        int ci_l = l >> 5, px_l = l & 31;
        t[ci_l][px_l] = xp[(size_t)ci_l * 4096 + px_l];
    }
    __syncthreads();
#pragma unroll
    for (int k = 0; k < 4; k++) {
        int l = tid + k * 256;
        int px_l = l >> 5, ci_l = l & 31;
        float v = t[ci_l][px_l];
        unsigned short h[3];
        split3(v, h);
        size_t o = ((size_t)b * 4096 + pt * 32 + px_l) * 512 + ct * 32 + ci_l;
        g_xs0[o] = h[0];
        g_xs1[o] = h[1];
        g_xs2[o] = h[2];
    }
}

__global__ void zerohist_kernel()
{
    g_hist[blockIdx.x * 1024 + threadIdx.x] = 0u;
}

// ---------------------------------------------------------------------------
// 3x3 conv 512->512 + bias + relu via mma.sync bf16 6-term emulated-fp32.
// CTA: 512 threads / 16 warps. M=128 co, N=128 px (2 rows). Warp tile m32n32.
// 72 chunks of 64 ci at fixed (dy,dx), double-buffered cp.async staging.
// Inner loop per k16-slice amortizes fragments across all 6 split-terms:
// 12 LDSM per 48 MMAs (vs 24 before) — halves SMEM crossbar traffic.
// P drains every k16-slice (chain 6) -> accuracy >= R11 config.
// ---------------------------------------------------------------------------
__global__ __launch_bounds__(512, 1) void conv_mma_kernel(
    const float* __restrict__ x, const float* __restrict__ bias)
{
    extern __shared__ __align__(16) char dsm[];
    const unsigned raw  = smem_u32(dsm);
    const unsigned base = (raw + 1023u) & ~1023u;  // 1024-aligned tiles

    const int tid = threadIdx.x;
    const int wid = tid >> 5;
    const int lid = tid & 31;
    const int m0  = blockIdx.x * 128;
    const int b   = blockIdx.y >> 5;
    const int y0  = (blockIdx.y & 31) * 2;

    const int mh = wid >> 2;            // co block of 32 (0..3)
    const int nq = wid & 3;             // px block of 32 (0..3)
    const int rlow = lid & 15;
    const int chalf = (lid >> 4) * 16;

    float acc[2][4][4];
    float P[2][4][4];
#pragma unroll
    for (int i = 0; i < 2; i++)
#pragma unroll
        for (int j = 0; j < 4; j++)
#pragma unroll
            for (int r = 0; r < 4; r++) { acc[i][j][r] = 0.f; P[i][j][r] = 0.f; }

    auto stageAB = [&](int c, int s) {
        const int kk  = c >> 3;
        const int cic = c & 7;
        const int dy  = kk / 3, dx = kk - dy * 3;
        const int ci0 = cic * 64;
        const unsigned sb = base + (unsigned)s * 98304u;
        const unsigned* wp = g_wsplit + ((unsigned)(kk * 8 + cic) * 512 + m0) * 32;
#pragma unroll
        for (int it = 0; it < 2; it++) {
            int idx = tid + it * 512;
            int co = idx >> 3, seg = idx & 7;
            unsigned off = SWZ((unsigned)(co * 128 + seg * 16));
            const unsigned* sp = wp + co * 32 + seg * 4;
            CP16(sb + 49152u + off, sp);
            CP16(sb + 65536u + off, sp + TSTRIDE);
            CP16(sb + 81920u + off, sp + 2 * TSTRIDE);
        }
#pragma unroll
        for (int it = 0; it < 2; it++) {
            int idx = tid + it * 512;
            int px = idx >> 3, seg = idx & 7;
            int yy = y0 + (px >> 6) + dy - 1;
            int xx = (px & 63) + dx - 1;
            bool ok = ((unsigned)yy < 64u) && ((unsigned)xx < 64u);
            int yc = ok ? yy : 0, xc = ok ? xx : 0;
            size_t po = ((size_t)b * 4096 + (size_t)yc * 64 + xc) * 512
                        + ci0 + seg * 8;
            unsigned off = SWZ((unsigned)(px * 128 + seg * 16));
            int sz = ok ? 16 : 0;
            CP16Z(sb + off,          g_xs0 + po, sz);
            CP16Z(sb + 16384u + off, g_xs1 + po, sz);
            CP16Z(sb + 32768u + off, g_xs2 + po, sz);
        }
    };

    // 8 MMAs of one m32n32 term-pair from fragment arrays A[8], B[8]
    auto mma_pair = [&](const unsigned* A, const unsigned* B) {
#pragma unroll
        for (int mt = 0; mt < 2; mt++)
#pragma unroll
            for (int bn = 0; bn < 2; bn++) {
                MMA16816(P[mt][bn*2][0], P[mt][bn*2][1], P[mt][bn*2][2], P[mt][bn*2][3],
                         A[mt*4+0], A[mt*4+1], A[mt*4+2], A[mt*4+3],
                         B[bn*4+0], B[bn*4+2]);
                MMA16816(P[mt][bn*2+1][0], P[mt][bn*2+1][1], P[mt][bn*2+1][2], P[mt][bn*2+1][3],
                         A[mt*4+0], A[mt*4+1], A[mt*4+2], A[mt*4+3],
                         B[bn*4+1], B[bn*4+3]);
            }
    };

    auto drain = [&]() {
#pragma unroll
        for (int i = 0; i < 2; i++)
#pragma unroll
            for (int j = 0; j < 4; j++)
#pragma unroll
                for (int r = 0; r < 4; r++) { acc[i][j][r] += P[i][j][r]; P[i][j][r] = 0.f; }
    };

    stageAB(0, 0);
    CP_COMMIT();
    CP_WAIT0();
    __syncthreads();

    for (int c = 0; c < 72; c++) {
        const int s = c & 1;
        if (c + 1 < 72) {
            stageAB(c + 1, s ^ 1);
            CP_COMMIT();
        }

        const unsigned sb = base + (unsigned)s * 98304u;
        const unsigned Ab = sb + 49152u;
        const unsigned Bb = sb;
#pragma unroll
        for (int ks = 0; ks < 4; ks++) {
            const unsigned aoff0 = SWZ((unsigned)((mh * 32 + rlow) * 128 + ks * 32 + chalf));
            const unsigned aoff1 = SWZ((unsigned)((mh * 32 + 16 + rlow) * 128 + ks * 32 + chalf));
            const unsigned boff0 = SWZ((unsigned)((nq * 32 + rlow) * 128 + ks * 32 + chalf));
            const unsigned boff1 = SWZ((unsigned)((nq * 32 + 16 + rlow) * 128 + ks * 32 + chalf));
            unsigned A0[8], A1[8], B0[8], B1[8];
            // term0 fragments
            LDSM_X4(A0[0], A0[1], A0[2], A0[3], Ab + aoff0);
            LDSM_X4(A0[4], A0[5], A0[6], A0[7], Ab + aoff1);
            LDSM_X4(B0[0], B0[1], B0[2], B0[3], Bb + boff0);
            LDSM_X4(B0[4], B0[5], B0[6], B0[7], Bb + boff1);
            mma_pair(A0, B0);                       // a0*b0
            // term1 B
            LDSM_X4(B1[0], B1[1], B1[2], B1[3], Bb + 16384u + boff0);
            LDSM_X4(B1[4], B1[5], B1[6], B1[7], Bb + 16384u + boff1);
            mma_pair(A0, B1);                       // a0*b1
            // term1 A
            LDSM_X4(A1[0], A1[1], A1[2], A1[3], Ab + 16384u + aoff0);
            LDSM_X4(A1[4], A1[5], A1[6], A1[7], Ab + 16384u + aoff1);
            mma_pair(A1, B0);                       // a1*b0
            mma_pair(A1, B1);                       // a1*b1
            // term2 A (overwrite A1)
            LDSM_X4(A1[0], A1[1], A1[2], A1[3], Ab + 32768u + aoff0);
            LDSM_X4(A1[4], A1[5], A1[6], A1[7], Ab + 32768u + aoff1);
            mma_pair(A1, B0);                       // a2*b0
            // term2 B (overwrite B1)
            LDSM_X4(B1[0], B1[1], B1[2], B1[3], Bb + 32768u + boff0);
            LDSM_X4(B1[4], B1[5], B1[6], B1[7], Bb + 32768u + boff1);
            mma_pair(A0, B1);                       // a0*b2
            drain();                                // chain length 6
        }

        if (c + 1 < 72) CP_WAIT0();
        __syncthreads();
    }

    {
        const int gr = lid >> 2;
        const int qc = lid & 3;
#pragma unroll
        for (int mt = 0; mt < 2; mt++) {
#pragma unroll
            for (int hi = 0; hi < 2; hi++) {
                int co_l = mh * 32 + mt * 16 + hi * 8 + gr;
                float bb = bias[m0 + co_l];
                unsigned trow = base + (unsigned)co_l * 528u;
#pragma unroll
                for (int nn = 0; nn < 4; nn++) {
#pragma unroll
                    for (int lo = 0; lo < 2; lo++) {
                        int px = nq * 32 + nn * 8 + qc * 2 + lo;
                        float v = acc[mt][nn][hi * 2 + lo] + bb;
                        v = v > 0.f ? v : 0.f;
                        STS32(trow + (unsigned)px * 4u, __float_as_uint(v));
                    }
                }
            }
        }
    }
    __syncthreads();

    for (int idx = tid; idx < 4096; idx += 512) {
        int co = idx >> 5;
        int p4 = (idx & 31) * 4;
        unsigned a0, a1, a2, a3;
        asm volatile("ld.shared.v4.b32 {%0,%1,%2,%3}, [%4];"
                     : "=r"(a0), "=r"(a1), "=r"(a2), "=r"(a3)
                     : "r"(base + (unsigned)co * 528u + (unsigned)p4 * 4u));
        float* dst = g_h + (((size_t)b * 512 + m0 + co) * 64 + y0 + (p4 >> 6)) * 64
                     + (p4 & 63);
        *(float4*)dst = make_float4(__uint_as_float(a0), __uint_as_float(a1),
                                    __uint_as_float(a2), __uint_as_float(a3));
    }
}

// ---------------------------------------------------------------------------
// 1x1 heads + softmax fg + box decode + sort keys + score-bucket histogram
// ---------------------------------------------------------------------------
__global__ __launch_bounds__(128) void heads_kernel(
    const float* __restrict__ sw, const float* __restrict__ sb,
    const float* __restrict__ lw, const float* __restrict__ lb,
    float* __restrict__ out)
{
    __shared__ float ws[64 * 54];
    const int tid = threadIdx.x;
    const int pg  = blockIdx.x * 128 + tid;
    const int b   = pg >> 12;
    const int pix = pg & 4095;

    float acc[54];
#pragma unroll
    for (int c = 0; c < 54; c++) acc[c] = 0.f;

    for (int cc = 0; cc < 512; cc += 64) {
        for (int idx = tid; idx < 64 * 54; idx += 128) {
            int ci = idx / 54;
            int c  = idx - ci * 54;
            ws[idx] = (c < 18) ? sw[c * 512 + cc + ci]
                               : lw[(c - 18) * 512 + cc + ci];
        }
        __syncthreads();
#pragma unroll 4
        for (int ci = 0; ci < 64; ci++) {
            float v = g_h[((size_t)(b * 512 + cc + ci)) * 4096 + pix];
#pragma unroll
            for (int c = 0; c < 54; c++) acc[c] += v * ws[ci * 54 + c];
        }
        __syncthreads();
    }

    const int y  = pix >> 6;
    const int xq = pix & 63;
    const float sy = (float)(y * 16);
    const float sx = (float)(xq * 16);

#pragma unroll
    for (int k = 0; k < 9; k++) {
        const double RR[3] = {0.5, 1.0, 2.0};
        const double SS[3] = {8.0, 16.0, 32.0};
        double rr = RR[k / 3], ss = SS[k % 3];
        double hh = 16.0 * ss * sqrt(rr);
        double wd = 16.0 * ss * sqrt(1.0 / rr);
        float by1 = (float)(8.0 - hh * 0.5), bx1 = (float)(8.0 - wd * 0.5);
        float by2 = (float)(8.0 + hh * 0.5), bx2 = (float)(8.0 + wd * 0.5);
        float ay1 = sy + by1, ax1 = sx + bx1, ay2 = sy + by2, ax2 = sx + bx2;

        const int a = pix * 9 + k;
        if (b == 0) {
            float* ap = out + OFS_ANCH + (size_t)a * 4;
            ap[0] = ay1; ap[1] = ax1; ap[2] = ay2; ap[3] = ax2;
        }

        float s0 = acc[k * 2 + 0] + sb[k * 2 + 0];
        float s1 = acc[k * 2 + 1] + sb[k * 2 + 1];
        out[OFS_SCORES + (size_t)b * 73728 + (size_t)a * 2 + 0] = s0;
        out[OFS_SCORES + (size_t)b * 73728 + (size_t)a * 2 + 1] = s1;

        float d0 = acc[18 + k * 4 + 0] + lb[k * 4 + 0];
        float d1 = acc[18 + k * 4 + 1] + lb[k * 4 + 1];
        float d2 = acc[18 + k * 4 + 2] + lb[k * 4 + 2];
        float d3 = acc[18 + k * 4 + 3] + lb[k * 4 + 3];
        float* lp = out + OFS_LOCS + (size_t)b * 147456 + (size_t)a * 4;
        lp[0] = d0; lp[1] = d1; lp[2] = d2; lp[3] = d3;

        float ah = ay2 - ay1, aw = ax2 - ax1;
        float cy = ay1 + 0.5f * ah, cx = ax1 + 0.5f * aw;
        float cty = d0 * ah + cy, ctx = d1 * aw + cx;
        float th = expf(d2) * ah, tw = expf(d3) * aw;
        float cy1 = fminf(fmaxf(cty - 0.5f * th, 0.f), 1024.f);
        float cy2 = fminf(fmaxf(cty + 0.5f * th, 0.f), 1024.f);
        float cx1 = fminf(fmaxf(ctx - 0.5f * tw, 0.f), 1024.f);
        float cx2 = fminf(fmaxf(ctx + 0.5f * tw, 0.f), 1024.f);
        bool valid = (cy2 - cy1 >= 16.f) && (cx2 - cx1 >= 16.f);

        float m = fmaxf(s0, s1);
        float e0 = expf(s0 - m), e1 = expf(s1 - m);
        float p1 = e1 / (e0 + e1);

        g_boxes4[(size_t)b * A_TOTAL + a] = make_float4(cy1, cx1, cy2, cx2);

        unsigned long long key;
        if (valid) {
            unsigned u = __float_as_uint(p1);
            u = (u & 0x80000000u) ? ~u : (u | 0x80000000u);
            key = ((unsigned long long)(~u) << 32) | (unsigned)a;
        } else {
            key = (0xFF800000ull << 32) | (unsigned)a;  // -inf score
        }
        g_keys[(size_t)b * A_TOTAL + a] = key;
        atomicAdd(&g_hist[b * 65536 + (unsigned)(key >> 48)], 1u);
    }
}

// find bucket threshold covering rank NIN; also reset count + pad sel buffer
__global__ __launch_bounds__(1024) void select_kernel()
{
    const int b = blockIdx.x, tid = threadIdx.x;
    __shared__ int part[1024];
    const unsigned* h = g_hist + b * 65536;
    int s = 0;
    for (int k = 0; k < 64; k++) s += (int)h[tid * 64 + k];
    part[tid] = s;
    __syncthreads();
    for (int off = 1; off < 1024; off <<= 1) {
        int v = (tid >= off) ? part[tid - off] : 0;
        __syncthreads();
        part[tid] += v;
        __syncthreads();
    }
    int incl = part[tid];
    int excl = incl - s;
    if (excl < NIN && incl >= NIN) {
        int c = excl, T = tid * 64 + 63;
        for (int k = 0; k < 64; k++) {
            c += (int)h[tid * 64 + k];
            if (c >= NIN) { T = tid * 64 + k; break; }
        }
        g_thr[b] = T;
    }
    if (tid == 0) g_cnt[b] = 0;
    for (int i = tid; i < NSEL; i += 1024) g_sel[b * NSEL + i] = ~0ull;
}

__global__ void compact_sel_kernel()
{
    int i = blockIdx.x * 256 + threadIdx.x;
    int b = blockIdx.y;
    if (i >= A_TOTAL) return;
    unsigned long long key = g_keys[(size_t)b * A_TOTAL + i];
    if ((int)(unsigned)(key >> 48) <= g_thr[b]) {
        int p = atomicAdd(&g_cnt[b], 1);
        if (p < NSEL) g_sel[b * NSEL + p] = key;
    }
}

// per-batch smem bitonic sort of <=16384 selected keys, then gather top-6000
__global__ __launch_bounds__(1024) void sortsel_kernel()
{
    const int b = blockIdx.x, tid = threadIdx.x;
    extern __shared__ unsigned long long s[];
    for (int i = tid; i < NSEL; i += 1024) s[i] = g_sel[b * NSEL + i];
    __syncthreads();
    for (int k = 2; k <= NSEL; k <<= 1) {
        for (int j = k >> 1; j > 0; j >>= 1) {
            for (int t = tid; t < NSEL; t += 1024) {
                int ixj = t ^ j;
                if (ixj > t) {
                    unsigned long long A = s[t], B = s[ixj];
                    bool up = ((t & k) == 0);
                    if ((A > B) == up) { s[t] = B; s[ixj] = A; }
                }
            }
            __syncthreads();
        }
    }
    for (int i = tid; i < NIN; i += 1024) {
        unsigned long long key = s[i];
        unsigned idx = (unsigned)key;
        float4 bx = g_boxes4[(size_t)b * A_TOTAL + idx];
        g_bsort4[b * NIN + i] = bx;
        g_areas[b * NIN + i] = (bx.z - bx.x) * (bx.w - bx.y);
        g_keep[b * NIN + i] = (int)((key >> 63) == 0);
    }
}

// ---------------------------------------------------------------------------
// NMS stage 1 (parallel): suppression bitmask rows.
// ---------------------------------------------------------------------------
__global__ __launch_bounds__(256) void nmsmask_kernel()
{
    const int b = blockIdx.y;
    const int i = blockIdx.x * 8 + (threadIdx.x >> 5);
    const int lane = threadIdx.x & 31;
    if (i >= NIN) return;
    const float4* bx = g_bsort4 + (size_t)b * NIN;
    const float*  ar = g_areas + b * NIN;
    float4 bi = bx[i];
    float  ai = ar[i];
    unsigned long long* row = g_nmsmask + ((size_t)b * NIN + i) * NWORDS;
    unsigned mlo = 0;
#pragma unroll 4
    for (int sc = 0; sc < 2 * NWORDS; sc++) {     // 188 subchunks of 32
        int j = sc * 32 + lane;
        bool sup = false;
        if (sc * 32 + 31 > i) {                   // subchunk contains j > i
            if (j > i && j < NIN) {
                float4 bj = bx[j];
                float yy1 = fmaxf(bi.x, bj.x);
                float xx1 = fmaxf(bi.y, bj.y);
                float yy2 = fminf(bi.z, bj.z);
                float xx2 = fminf(bi.w, bj.w);
                float inter = fmaxf(yy2 - yy1, 0.f) * fmaxf(xx2 - xx1, 0.f);
                float iou = inter / (ai + ar[j] - inter + 1e-9f);
                sup = iou > 0.7f;
            }
        }
        unsigned m = __ballot_sync(0xffffffffu, sup);
        if (sc & 1) {
            if (lane == 0)
                row[sc >> 1] = (unsigned long long)mlo
                             | ((unsigned long long)m << 32);
        } else {
            mlo = m;
        }
    }
}

// ---------------------------------------------------------------------------
// NMS stage 2 (serial, 1 warp per batch): greedy scan over register bitmap.
// ---------------------------------------------------------------------------
__global__ __launch_bounds__(32) void nmsscan_kernel()
{
    __shared__ __align__(16) unsigned long long ring[16][96];
    const int b = blockIdx.x;
    const int lane = threadIdx.x;
    const unsigned long long* mask = g_nmsmask + (size_t)b * NIN * NWORDS;
    const int* kin = g_keep + b * NIN;

    const int w0 = lane, w1 = lane + 32, w2 = lane + 64;
    unsigned long long k0 = 0, k1 = 0, k2 = 0;
#pragma unroll 1
    for (int k = 0; k < 64; k++) {
        k0 |= (unsigned long long)(kin[w0 * 64 + k] & 1) << k;
        k1 |= (unsigned long long)(kin[w1 * 64 + k] & 1) << k;
        int j2 = w2 * 64 + k;
        if (w2 < NWORDS && j2 < NIN)
            k2 |= (unsigned long long)(kin[j2] & 1) << k;
    }

    const unsigned rbase = smem_u32(ring);
    auto issue = [&](int i) {
        unsigned dst = rbase + (unsigned)(i & 15) * 768u;
        const unsigned long long* src = mask + (size_t)i * NWORDS;
        CP8(dst + (unsigned)lane * 8u, src + lane);
        CP8(dst + (unsigned)(lane + 32) * 8u, src + lane + 32);
        if (lane < NWORDS - 64) CP8(dst + (unsigned)(lane + 64) * 8u, src + lane + 64);
        CP_COMMIT();
    };
    for (int i = 0; i < 15; i++) issue(i);

    unsigned long long cur = __shfl_sync(0xffffffffu, k0, 0);

    for (int i = 0; i < NIN; i++) {
        asm volatile("cp.async.wait_group 14;");
        if ((i & 63) == 0 && i) {
            int w = i >> 6;
            unsigned long long kw = (w < 32) ? k0 : ((w < 64) ? k1 : k2);
            cur = __shfl_sync(0xffffffffu, kw, w & 31);
        }
        bool alive = (cur >> (i & 63)) & 1ull;
        if (alive) {
            unsigned saddr = rbase + (unsigned)(i & 15) * 768u;
            unsigned long long r0, r1, r2 = 0;
            LDS64(r0, saddr + (unsigned)lane * 8u);
            LDS64(r1, saddr + (unsigned)(lane + 32) * 8u);
            if (lane < NWORDS - 64) LDS64(r2, saddr + (unsigned)(lane + 64) * 8u);
            k0 &= ~r0;
            k1 &= ~r1;
            k2 &= ~r2;
            int w = i >> 6;
            unsigned long long rw = (w < 32) ? r0 : ((w < 64) ? r1 : r2);
            rw = __shfl_sync(0xffffffffu, rw, w & 31);
            cur &= ~rw;
        }
        if (i + 15 < NIN) issue(i + 15);
    }

    int* kout = g_keep + b * NIN;
#pragma unroll 1
    for (int k = 0; k < 64; k++) {
        kout[w0 * 64 + k] = (int)((k0 >> k) & 1ull);
        kout[w1 * 64 + k] = (int)((k1 >> k) & 1ull);
        int j2 = w2 * 64 + k;
        if (w2 < NWORDS && j2 < NIN)
            kout[j2] = (int)((k2 >> k) & 1ull);
    }
}

// compact kept boxes into first 300 rows; zero-fill the rest; roi_indices
__global__ __launch_bounds__(1024) void compact_kernel(float* __restrict__ out)
{
    const int b = blockIdx.x;
    const int tid = threadIdx.x;
    __shared__ int csum[1024];

    const int base = tid * 6;
    int local[6];
    int cnt = 0;
#pragma unroll
    for (int e = 0; e < 6; e++) {
        int i = base + e;
        int k = (i < NIN) ? g_keep[b * NIN + i] : 0;
        local[e] = k;
        cnt += k;
    }
    csum[tid] = cnt;
    __syncthreads();
    for (int off = 1; off < 1024; off <<= 1) {
        int v = (tid >= off) ? csum[tid - off] : 0;
        __syncthreads();
        csum[tid] += v;
        __syncthreads();
    }
    int rank = csum[tid] - cnt;

    float* rois = out + OFS_ROIS + (size_t)b * 1200;
    for (int i = tid; i < 1200; i += 1024) rois[i] = 0.f;
    float* ridx = out + OFS_RIDX + (size_t)b * 300;
    for (int i = tid; i < 300; i += 1024) ridx[i] = (float)b;
    __syncthreads();

    int r = rank;
#pragma unroll
    for (int e = 0; e < 6; e++) {
        int i = base + e;
        if (i < NIN && local[e]) {
            if (r < NOUTB) {
                float4 bx = g_bsort4[b * NIN + i];
                rois[r * 4 + 0] = bx.x;
                rois[r * 4 + 1] = bx.y;
                rois[r * 4 + 2] = bx.z;
                rois[r * 4 + 3] = bx.w;
            }
            r++;
        }
    }
}

extern "C" void kernel_launch(void* const* d_in, const int* in_sizes, int n_in,
                              void* d_out, int out_size)
{
    const float* x       = (const float*)d_in[0];
    const float* conv_w  = (const float*)d_in[1];
    const float* conv_b  = (const float*)d_in[2];
    const float* score_w = (const float*)d_in[3];
    const float* score_b = (const float*)d_in[4];
    const float* loc_w   = (const float*)d_in[5];
    const float* loc_b   = (const float*)d_in[6];
    float* out = (float*)d_out;

    const int CONV_SMEM = 1024 + 2 * 98304;   // align slack + 2 buffer sets
    cudaFuncSetAttribute(conv_mma_kernel,
        cudaFuncAttributeMaxDynamicSharedMemorySize, CONV_SMEM);
    cudaFuncSetAttribute(sortsel_kernel,
        cudaFuncAttributeMaxDynamicSharedMemorySize, NSEL * 8);

    wsplit_kernel<<<4608, 256>>>(conv_w);
    xsplit_kernel<<<8192, 256>>>(x);
    zerohist_kernel<<<256, 1024>>>();
    conv_mma_kernel<<<dim3(4, 128), 512, CONV_SMEM>>>(x, conv_b);
    heads_kernel<<<128, 128>>>(score_w, score_b, loc_w, loc_b, out);
    select_kernel<<<BATCH, 1024>>>();
    compact_sel_kernel<<<dim3(144, BATCH), 256>>>();
    sortsel_kernel<<<BATCH, 1024, NSEL * 8>>>();
    nmsmask_kernel<<<dim3(750, BATCH), 256>>>();
    nmsscan_kernel<<<BATCH, 32>>>();
    compact_kernel<<<BATCH, 1024>>>(out);
}

// round 16
// speedup vs baseline: 5.5861x; 1.0489x over previous
#include <cuda_runtime.h>
#include <cuda_bf16.h>
#include <math.h>

#define A_TOTAL 36864
#define NIN     6000
#define NOUTB   300
#define BATCH   4
#define NSEL    16384
#define NWORDS  94

// output layout (float32, concatenated reference tuple)
#define OFS_SCORES 0
#define OFS_LOCS   294912
#define OFS_ROIS   884736
#define OFS_RIDX   889536
#define OFS_ANCH   890736

#define TSTRIDE (9u * 8u * 512u * 32u)   // u32 elements per split-term plane

// scratch (device globals; no allocation allowed)
__device__ float  g_h[BATCH * 512 * 4096];
__device__ unsigned g_wsplit[3 * 9 * 8 * 512 * 32];   // [term][kk][cic][co][j2] bf16x2
__device__ unsigned short g_xs0[BATCH * 4096 * 512];  // channel-last bf16 term planes
__device__ unsigned short g_xs1[BATCH * 4096 * 512];
__device__ unsigned short g_xs2[BATCH * 4096 * 512];
__device__ float4 g_boxes4[BATCH * A_TOTAL];
__device__ unsigned long long g_keys[BATCH * A_TOTAL];
__device__ unsigned g_hist[BATCH * 65536];
__device__ int    g_thr[BATCH];
__device__ int    g_cnt[BATCH];
__device__ unsigned long long g_sel[BATCH * NSEL];
__device__ float4 g_bsort4[BATCH * NIN];
__device__ float  g_areas[BATCH * NIN];
__device__ int    g_keep[BATCH * NIN];
__device__ unsigned long long g_nmsmask[(size_t)BATCH * NIN * NWORDS];

// ---------------------------------------------------------------------------
// helpers
// ---------------------------------------------------------------------------
#define SWZ(o)   ((o) ^ (((o) >> 3) & 0x70))
#define SWZ64(o) ((o) ^ (((o) >> 3) & 0x30))

static __device__ __forceinline__ unsigned smem_u32(const void* p) {
    unsigned a;
    asm("{ .reg .u64 t; cvta.to.shared.u64 t, %1; cvt.u32.u64 %0, t; }"
        : "=r"(a) : "l"(p));
    return a;
}
// no "memory" clobber — __syncthreads() is the fence
#define STS32(addr, val) \
    asm volatile("st.shared.b32 [%0], %1;" :: "r"(addr), "r"(val))

#define LDS64(d, a) \
    asm volatile("ld.shared.b64 %0, [%1];" : "=l"(d) : "r"(a))

#define CP8(dst, src) \
    asm volatile("cp.async.ca.shared.global [%0], [%1], 8;" \
                 :: "r"(dst), "l"(src))
#define CP16(dst, src) \
    asm volatile("cp.async.cg.shared.global [%0], [%1], 16;" \
                 :: "r"(dst), "l"(src))
#define CP16Z(dst, src, sz) \
    asm volatile("cp.async.cg.shared.global [%0], [%1], 16, %2;" \
                 :: "r"(dst), "l"(src), "r"(sz))
#define CP_COMMIT() asm volatile("cp.async.commit_group;")
#define CP_WAIT0()  asm volatile("cp.async.wait_group 0;")

#define LDSM_X4(r0, r1, r2, r3, addr) \
    asm volatile("ldmatrix.sync.aligned.m8n8.x4.shared.b16 {%0,%1,%2,%3}, [%4];" \
                 : "=r"(r0), "=r"(r1), "=r"(r2), "=r"(r3) : "r"(addr))

#define MMA16816(d0, d1, d2, d3, a0, a1, a2, a3, b0, b1) \
    asm volatile("mma.sync.aligned.m16n8k16.row.col.f32.bf16.bf16.f32 " \
                 "{%0,%1,%2,%3}, {%4,%5,%6,%7}, {%8,%9}, {%0,%1,%2,%3};" \
                 : "+f"(d0), "+f"(d1), "+f"(d2), "+f"(d3) \
                 : "r"(a0), "r"(a1), "r"(a2), "r"(a3), "r"(b0), "r"(b1))

static __device__ __forceinline__ void split3(float v, unsigned short o[3]) {
    __nv_bfloat16 b0 = __float2bfloat16_rn(v);
    float f0 = __bfloat162float(b0);
    float r1 = v - f0;
    __nv_bfloat16 b1 = __float2bfloat16_rn(r1);
    float f1 = __bfloat162float(b1);
    __nv_bfloat16 b2 = __float2bfloat16_rn(r1 - f1);
    o[0] = __bfloat16_as_ushort(b0);
    o[1] = __bfloat16_as_ushort(b1);
    o[2] = __bfloat16_as_ushort(b2);
}

// ---------------------------------------------------------------------------
// weight split precompute: w[co][ci][kk] -> 3 bf16 planes [kk][cic][co][j2]
// ---------------------------------------------------------------------------
__global__ void wsplit_kernel(const float* __restrict__ w)
{
    int idx = blockIdx.x * 256 + threadIdx.x;   // 9*8*512*32 = 1,179,648 exact
    int j2  = idx & 31;
    int co  = (idx >> 5) & 511;
    int cic = (idx >> 14) & 7;
    int kk  = idx >> 17;
    if (kk >= 9) return;
    int ci = cic * 64 + j2 * 2;
    float v0 = w[((size_t)co * 512 + ci) * 9 + kk];
    float v1 = w[((size_t)co * 512 + ci + 1) * 9 + kk];
    unsigned short h[3], g[3];
    split3(v0, h);
    split3(v1, g);
    unsigned base = (((unsigned)kk * 8 + cic) * 512 + co) * 32 + j2;
#pragma unroll
    for (int t = 0; t < 3; t++)
        g_wsplit[t * TSTRIDE + base] = (unsigned)h[t] | ((unsigned)g[t] << 16);
}

// ---------------------------------------------------------------------------
// input split precompute: x[b][ci][y][x] f32 -> channel-last bf16 planes
// ---------------------------------------------------------------------------
__global__ __launch_bounds__(256) void xsplit_kernel(const float* __restrict__ x)
{
    __shared__ float t[32][33];
    const int bid = blockIdx.x;          // 4 * 16 * 128 = 8192 blocks
    const int pt  = bid & 127;           // pixel tile (32 px)
    const int ct  = (bid >> 7) & 15;     // ci tile (32 ci)
    const int b   = bid >> 11;
    const int tid = threadIdx.x;

    const float* xp = x + ((size_t)b * 512 + ct * 32) * 4096 + pt * 32;
#pragma unroll
    for (int k = 0; k < 4; k++) {
        int l = tid + k * 256;
        int ci_l = l >> 5, px_l = l & 31;
        t[ci_l][px_l] = xp[(size_t)ci_l * 4096 + px_l];
    }
    __syncthreads();
#pragma unroll
    for (int k = 0; k < 4; k++) {
        int l = tid + k * 256;
        int px_l = l >> 5, ci_l = l & 31;
        float v = t[ci_l][px_l];
        unsigned short h[3];
        split3(v, h);
        size_t o = ((size_t)b * 4096 + pt * 32 + px_l) * 512 + ct * 32 + ci_l;
        g_xs0[o] = h[0];
        g_xs1[o] = h[1];
        g_xs2[o] = h[2];
    }
}

__global__ void zerohist_kernel()
{
    g_hist[blockIdx.x * 1024 + threadIdx.x] = 0u;
}

// ---------------------------------------------------------------------------
// 3x3 conv 512->512 + bias + relu via mma.sync bf16 6-term emulated-fp32.
// CTA: 256 threads / 8 warps, M=64 co, N=128 px (2 rows). Warp tile m32n32.
// 144 chunks of 32 ci at fixed (dy,dx); 64B tile rows, SW64 swizzle;
// double-buffered cp.async staging; 2 CTAs/SM (72KB smem + 128 regs each).
// Fragment reuse: 12 LDSM per 48 MMAs per k16-slice; drain once per chunk
// (RZ chain 12 <= the 20 that passed in R13).
// ---------------------------------------------------------------------------
__global__ __launch_bounds__(256, 2) void conv_mma_kernel(
    const float* __restrict__ x, const float* __restrict__ bias)
{
    extern __shared__ __align__(16) char dsm[];
    const unsigned raw  = smem_u32(dsm);
    const unsigned base = (raw + 1023u) & ~1023u;  // 1024-aligned tiles

    const int tid = threadIdx.x;
    const int wid = tid >> 5;
    const int lid = tid & 31;
    const int m0  = blockIdx.x * 64;
    const int b   = blockIdx.y >> 5;
    const int y0  = (blockIdx.y & 31) * 2;

    const int mh = wid >> 2;            // co block of 32 (0..1)
    const int nq = wid & 3;             // px block of 32 (0..3)
    const int rlow = lid & 15;
    const int chalf = (lid >> 4) * 16;

    float acc[2][4][4];
    float P[2][4][4];
#pragma unroll
    for (int i = 0; i < 2; i++)
#pragma unroll
        for (int j = 0; j < 4; j++)
#pragma unroll
            for (int r = 0; r < 4; r++) { acc[i][j][r] = 0.f; P[i][j][r] = 0.f; }

    // set layout (stride 36864): B0,B1,B2 @ 0/8K/16K, A0,A1,A2 @ 24K/28K/32K
    auto stageAB = [&](int c, int s) {
        const int kk   = c >> 4;           // 0..8
        const int sub  = c & 15;           // 32-ci subchunk
        const int cic  = sub >> 1;
        const int half = sub & 1;
        const int dy   = kk / 3, dx = kk - dy * 3;
        const int ci0  = sub * 32;
        const unsigned sb = base + (unsigned)s * 36864u;
        // A: 64 co x 64B per term (copy from pre-split weights)
        const unsigned* wp = g_wsplit
            + ((unsigned)(kk * 8 + cic) * 512 + m0) * 32 + half * 16;
#pragma unroll
        for (int it = 0; it < 3; it++) {
            int idx = tid + it * 256;      // 0..767
            int term = idx >> 8;
            int r = idx & 255;
            int co = r >> 2, seg = r & 3;
            unsigned off = SWZ64((unsigned)(co * 64 + seg * 16));
            CP16(sb + 24576u + (unsigned)term * 4096u + off,
                 wp + (unsigned)term * TSTRIDE + co * 32 + seg * 4);
        }
        // B: 128 px x 64B per term (channel-last pre-split input)
#pragma unroll
        for (int it = 0; it < 6; it++) {
            int idx = tid + it * 256;      // 0..1535
            int term = idx >> 9;
            int r = idx & 511;
            int px = r >> 2, seg = r & 3;
            int yy = y0 + (px >> 6) + dy - 1;
            int xx = (px & 63) + dx - 1;
            bool ok = ((unsigned)yy < 64u) && ((unsigned)xx < 64u);
            int yc = ok ? yy : 0, xc = ok ? xx : 0;
            size_t po = ((size_t)b * 4096 + (size_t)yc * 64 + xc) * 512
                        + ci0 + seg * 8;
            const unsigned short* plane = (term == 0) ? g_xs0
                                        : (term == 1) ? g_xs1 : g_xs2;
            unsigned off = SWZ64((unsigned)(px * 64 + seg * 16));
            CP16Z(sb + (unsigned)term * 8192u + off, plane + po, ok ? 16 : 0);
        }
    };

    // 8 MMAs of one m32n32 term-pair from fragment arrays A[8], B[8]
    auto mma_pair = [&](const unsigned* A, const unsigned* B) {
#pragma unroll
        for (int mt = 0; mt < 2; mt++)
#pragma unroll
            for (int bn = 0; bn < 2; bn++) {
                MMA16816(P[mt][bn*2][0], P[mt][bn*2][1], P[mt][bn*2][2], P[mt][bn*2][3],
                         A[mt*4+0], A[mt*4+1], A[mt*4+2], A[mt*4+3],
                         B[bn*4+0], B[bn*4+2]);
                MMA16816(P[mt][bn*2+1][0], P[mt][bn*2+1][1], P[mt][bn*2+1][2], P[mt][bn*2+1][3],
                         A[mt*4+0], A[mt*4+1], A[mt*4+2], A[mt*4+3],
                         B[bn*4+1], B[bn*4+3]);
            }
    };

    auto drain = [&]() {
#pragma unroll
        for (int i = 0; i < 2; i++)
#pragma unroll
            for (int j = 0; j < 4; j++)
#pragma unroll
                for (int r = 0; r < 4; r++) { acc[i][j][r] += P[i][j][r]; P[i][j][r] = 0.f; }
    };

    stageAB(0, 0);
    CP_COMMIT();
    CP_WAIT0();
    __syncthreads();

    for (int c = 0; c < 144; c++) {
        const int s = c & 1;
        if (c + 1 < 144) {
            stageAB(c + 1, s ^ 1);
            CP_COMMIT();
        }

        const unsigned sb = base + (unsigned)s * 36864u;
        const unsigned Ab = sb + 24576u;
        const unsigned Bb = sb;
#pragma unroll
        for (int ks = 0; ks < 2; ks++) {
            const unsigned aoff0 = SWZ64((unsigned)((mh * 32 + rlow) * 64 + ks * 32 + chalf));
            const unsigned aoff1 = SWZ64((unsigned)((mh * 32 + 16 + rlow) * 64 + ks * 32 + chalf));
            const unsigned boff0 = SWZ64((unsigned)((nq * 32 + rlow) * 64 + ks * 32 + chalf));
            const unsigned boff1 = SWZ64((unsigned)((nq * 32 + 16 + rlow) * 64 + ks * 32 + chalf));
            unsigned A0[8], A1[8], B0[8], B1[8];
            // term0 fragments
            LDSM_X4(A0[0], A0[1], A0[2], A0[3], Ab + aoff0);
            LDSM_X4(A0[4], A0[5], A0[6], A0[7], Ab + aoff1);
            LDSM_X4(B0[0], B0[1], B0[2], B0[3], Bb + boff0);
            LDSM_X4(B0[4], B0[5], B0[6], B0[7], Bb + boff1);
            mma_pair(A0, B0);                       // a0*b0
            // term1 B
            LDSM_X4(B1[0], B1[1], B1[2], B1[3], Bb + 8192u + boff0);
            LDSM_X4(B1[4], B1[5], B1[6], B1[7], Bb + 8192u + boff1);
            mma_pair(A0, B1);                       // a0*b1
            // term1 A
            LDSM_X4(A1[0], A1[1], A1[2], A1[3], Ab + 4096u + aoff0);
            LDSM_X4(A1[4], A1[5], A1[6], A1[7], Ab + 4096u + aoff1);
            mma_pair(A1, B0);                       // a1*b0
            mma_pair(A1, B1);                       // a1*b1
            // term2 A (overwrite A1)
            LDSM_X4(A1[0], A1[1], A1[2], A1[3], Ab + 8192u + aoff0);
            LDSM_X4(A1[4], A1[5], A1[6], A1[7], Ab + 8192u + aoff1);
            mma_pair(A1, B0);                       // a2*b0
            // term2 B (overwrite B1)
            LDSM_X4(B1[0], B1[1], B1[2], B1[3], Bb + 16384u + boff0);
            LDSM_X4(B1[4], B1[5], B1[6], B1[7], Bb + 16384u + boff1);
            mma_pair(A0, B1);                       // a0*b2
        }
        drain();                                    // chain length 12

        if (c + 1 < 144) CP_WAIT0();
        __syncthreads();
    }

    // epilogue: accs -> bias+relu -> smem transpose [co][px] (row stride 132 f32)
    {
        const int gr = lid >> 2;
        const int qc = lid & 3;
#pragma unroll
        for (int mt = 0; mt < 2; mt++) {
#pragma unroll
            for (int hi = 0; hi < 2; hi++) {
                int co_l = mh * 32 + mt * 16 + hi * 8 + gr;   // 0..63
                float bb = bias[m0 + co_l];
                unsigned trow = base + (unsigned)co_l * 528u;
#pragma unroll
                for (int nn = 0; nn < 4; nn++) {
#pragma unroll
                    for (int lo = 0; lo < 2; lo++) {
                        int px = nq * 32 + nn * 8 + qc * 2 + lo;
                        float v = acc[mt][nn][hi * 2 + lo] + bb;
                        v = v > 0.f ? v : 0.f;
                        STS32(trow + (unsigned)px * 4u, __float_as_uint(v));
                    }
                }
            }
        }
    }
    __syncthreads();

    // coalesced write-out: g_h[b][m0+co][y0 + px/64][px%64]
    for (int idx = tid; idx < 2048; idx += 256) {
        int co = idx >> 5;                 // 0..63
        int p4 = (idx & 31) * 4;
        unsigned a0, a1, a2, a3;
        asm volatile("ld.shared.v4.b32 {%0,%1,%2,%3}, [%4];"
                     : "=r"(a0), "=r"(a1), "=r"(a2), "=r"(a3)
                     : "r"(base + (unsigned)co * 528u + (unsigned)p4 * 4u));
        float* dst = g_h + (((size_t)b * 512 + m0 + co) * 64 + y0 + (p4 >> 6)) * 64
                     + (p4 & 63);
        *(float4*)dst = make_float4(__uint_as_float(a0), __uint_as_float(a1),
                                    __uint_as_float(a2), __uint_as_float(a3));
    }
}

// ---------------------------------------------------------------------------
// 1x1 heads + softmax fg + box decode + sort keys + score-bucket histogram
// ---------------------------------------------------------------------------
__global__ __launch_bounds__(128) void heads_kernel(
    const float* __restrict__ sw, const float* __restrict__ sb,
    const float* __restrict__ lw, const float* __restrict__ lb,
    float* __restrict__ out)
{
    __shared__ float ws[64 * 54];
    const int tid = threadIdx.x;
    const int pg  = blockIdx.x * 128 + tid;
    const int b   = pg >> 12;
    const int pix = pg & 4095;

    float acc[54];
#pragma unroll
    for (int c = 0; c < 54; c++) acc[c] = 0.f;

    for (int cc = 0; cc < 512; cc += 64) {
        for (int idx = tid; idx < 64 * 54; idx += 128) {
            int ci = idx / 54;
            int c  = idx - ci * 54;
            ws[idx] = (c < 18) ? sw[c * 512 + cc + ci]
                               : lw[(c - 18) * 512 + cc + ci];
        }
        __syncthreads();
#pragma unroll 4
        for (int ci = 0; ci < 64; ci++) {
            float v = g_h[((size_t)(b * 512 + cc + ci)) * 4096 + pix];
#pragma unroll
            for (int c = 0; c < 54; c++) acc[c] += v * ws[ci * 54 + c];
        }
        __syncthreads();
    }

    const int y  = pix >> 6;
    const int xq = pix & 63;
    const float sy = (float)(y * 16);
    const float sx = (float)(xq * 16);

#pragma unroll
    for (int k = 0; k < 9; k++) {
        const double RR[3] = {0.5, 1.0, 2.0};
        const double SS[3] = {8.0, 16.0, 32.0};
        double rr = RR[k / 3], ss = SS[k % 3];
        double hh = 16.0 * ss * sqrt(rr);
        double wd = 16.0 * ss * sqrt(1.0 / rr);
        float by1 = (float)(8.0 - hh * 0.5), bx1 = (float)(8.0 - wd * 0.5);
        float by2 = (float)(8.0 + hh * 0.5), bx2 = (float)(8.0 + wd * 0.5);
        float ay1 = sy + by1, ax1 = sx + bx1, ay2 = sy + by2, ax2 = sx + bx2;

        const int a = pix * 9 + k;
        if (b == 0) {
            float* ap = out + OFS_ANCH + (size_t)a * 4;
            ap[0] = ay1; ap[1] = ax1; ap[2] = ay2; ap[3] = ax2;
        }

        float s0 = acc[k * 2 + 0] + sb[k * 2 + 0];
        float s1 = acc[k * 2 + 1] + sb[k * 2 + 1];
        out[OFS_SCORES + (size_t)b * 73728 + (size_t)a * 2 + 0] = s0;
        out[OFS_SCORES + (size_t)b * 73728 + (size_t)a * 2 + 1] = s1;

        float d0 = acc[18 + k * 4 + 0] + lb[k * 4 + 0];
        float d1 = acc[18 + k * 4 + 1] + lb[k * 4 + 1];
        float d2 = acc[18 + k * 4 + 2] + lb[k * 4 + 2];
        float d3 = acc[18 + k * 4 + 3] + lb[k * 4 + 3];
        float* lp = out + OFS_LOCS + (size_t)b * 147456 + (size_t)a * 4;
        lp[0] = d0; lp[1] = d1; lp[2] = d2; lp[3] = d3;

        float ah = ay2 - ay1, aw = ax2 - ax1;
        float cy = ay1 + 0.5f * ah, cx = ax1 + 0.5f * aw;
        float cty = d0 * ah + cy, ctx = d1 * aw + cx;
        float th = expf(d2) * ah, tw = expf(d3) * aw;
        float cy1 = fminf(fmaxf(cty - 0.5f * th, 0.f), 1024.f);
        float cy2 = fminf(fmaxf(cty + 0.5f * th, 0.f), 1024.f);
        float cx1 = fminf(fmaxf(ctx - 0.5f * tw, 0.f), 1024.f);
        float cx2 = fminf(fmaxf(ctx + 0.5f * tw, 0.f), 1024.f);
        bool valid = (cy2 - cy1 >= 16.f) && (cx2 - cx1 >= 16.f);

        float m = fmaxf(s0, s1);
        float e0 = expf(s0 - m), e1 = expf(s1 - m);
        float p1 = e1 / (e0 + e1);

        g_boxes4[(size_t)b * A_TOTAL + a] = make_float4(cy1, cx1, cy2, cx2);

        unsigned long long key;
        if (valid) {
            unsigned u = __float_as_uint(p1);
            u = (u & 0x80000000u) ? ~u : (u | 0x80000000u);
            key = ((unsigned long long)(~u) << 32) | (unsigned)a;
        } else {
            key = (0xFF800000ull << 32) | (unsigned)a;  // -inf score
        }
        g_keys[(size_t)b * A_TOTAL + a] = key;
        atomicAdd(&g_hist[b * 65536 + (unsigned)(key >> 48)], 1u);
    }
}

// find bucket threshold covering rank NIN; also reset count + pad sel buffer
__global__ __launch_bounds__(1024) void select_kernel()
{
    const int b = blockIdx.x, tid = threadIdx.x;
    __shared__ int part[1024];
    const unsigned* h = g_hist + b * 65536;
    int s = 0;
    for (int k = 0; k < 64; k++) s += (int)h[tid * 64 + k];
    part[tid] = s;
    __syncthreads();
    for (int off = 1; off < 1024; off <<= 1) {
        int v = (tid >= off) ? part[tid - off] : 0;
        __syncthreads();
        part[tid] += v;
        __syncthreads();
    }
    int incl = part[tid];
    int excl = incl - s;
    if (excl < NIN && incl >= NIN) {
        int c = excl, T = tid * 64 + 63;
        for (int k = 0; k < 64; k++) {
            c += (int)h[tid * 64 + k];
            if (c >= NIN) { T = tid * 64 + k; break; }
        }
        g_thr[b] = T;
    }
    if (tid == 0) g_cnt[b] = 0;
    for (int i = tid; i < NSEL; i += 1024) g_sel[b * NSEL + i] = ~0ull;
}

__global__ void compact_sel_kernel()
{
    int i = blockIdx.x * 256 + threadIdx.x;
    int b = blockIdx.y;
    if (i >= A_TOTAL) return;
    unsigned long long key = g_keys[(size_t)b * A_TOTAL + i];
    if ((int)(unsigned)(key >> 48) <= g_thr[b]) {
        int p = atomicAdd(&g_cnt[b], 1);
        if (p < NSEL) g_sel[b * NSEL + p] = key;
    }
}

// per-batch smem bitonic sort of <=16384 selected keys, then gather top-6000
__global__ __launch_bounds__(1024) void sortsel_kernel()
{
    const int b = blockIdx.x, tid = threadIdx.x;
    extern __shared__ unsigned long long s[];
    for (int i = tid; i < NSEL; i += 1024) s[i] = g_sel[b * NSEL + i];
    __syncthreads();
    for (int k = 2; k <= NSEL; k <<= 1) {
        for (int j = k >> 1; j > 0; j >>= 1) {
            for (int t = tid; t < NSEL; t += 1024) {
                int ixj = t ^ j;
                if (ixj > t) {
                    unsigned long long A = s[t], B = s[ixj];
                    bool up = ((t & k) == 0);
                    if ((A > B) == up) { s[t] = B; s[ixj] = A; }
                }
            }
            __syncthreads();
        }
    }
    for (int i = tid; i < NIN; i += 1024) {
        unsigned long long key = s[i];
        unsigned idx = (unsigned)key;
        float4 bx = g_boxes4[(size_t)b * A_TOTAL + idx];
        g_bsort4[b * NIN + i] = bx;
        g_areas[b * NIN + i] = (bx.z - bx.x) * (bx.w - bx.y);
        g_keep[b * NIN + i] = (int)((key >> 63) == 0);
    }
}

// ---------------------------------------------------------------------------
// NMS stage 1 (parallel): suppression bitmask rows.
// ---------------------------------------------------------------------------
__global__ __launch_bounds__(256) void nmsmask_kernel()
{
    const int b = blockIdx.y;
    const int i = blockIdx.x * 8 + (threadIdx.x >> 5);
    const int lane = threadIdx.x & 31;
    if (i >= NIN) return;
    const float4* bx = g_bsort4 + (size_t)b * NIN;
    const float*  ar = g_areas + b * NIN;
    float4 bi = bx[i];
    float  ai = ar[i];
    unsigned long long* row = g_nmsmask + ((size_t)b * NIN + i) * NWORDS;
    unsigned mlo = 0;
#pragma unroll 4
    for (int sc = 0; sc < 2 * NWORDS; sc++) {     // 188 subchunks of 32
        int j = sc * 32 + lane;
        bool sup = false;
        if (sc * 32 + 31 > i) {                   // subchunk contains j > i
            if (j > i && j < NIN) {
                float4 bj = bx[j];
                float yy1 = fmaxf(bi.x, bj.x);
                float xx1 = fmaxf(bi.y, bj.y);
                float yy2 = fminf(bi.z, bj.z);
                float xx2 = fminf(bi.w, bj.w);
                float inter = fmaxf(yy2 - yy1, 0.f) * fmaxf(xx2 - xx1, 0.f);
                float iou = inter / (ai + ar[j] - inter + 1e-9f);
                sup = iou > 0.7f;
            }
        }
        unsigned m = __ballot_sync(0xffffffffu, sup);
        if (sc & 1) {
            if (lane == 0)
                row[sc >> 1] = (unsigned long long)mlo
                             | ((unsigned long long)m << 32);
        } else {
            mlo = m;
        }
    }
}

// ---------------------------------------------------------------------------
// NMS stage 2 (serial, 1 warp per batch): greedy scan over register bitmap.
// ---------------------------------------------------------------------------
__global__ __launch_bounds__(32) void nmsscan_kernel()
{
    __shared__ __align__(16) unsigned long long ring[16][96];
    const int b = blockIdx.x;
    const int lane = threadIdx.x;
    const unsigned long long* mask = g_nmsmask + (size_t)b * NIN * NWORDS;
    const int* kin = g_keep + b * NIN;

    const int w0 = lane, w1 = lane + 32, w2 = lane + 64;
    unsigned long long k0 = 0, k1 = 0, k2 = 0;
#pragma unroll 1
    for (int k = 0; k < 64; k++) {
        k0 |= (unsigned long long)(kin[w0 * 64 + k] & 1) << k;
        k1 |= (unsigned long long)(kin[w1 * 64 + k] & 1) << k;
        int j2 = w2 * 64 + k;
        if (w2 < NWORDS && j2 < NIN)
            k2 |= (unsigned long long)(kin[j2] & 1) << k;
    }

    const unsigned rbase = smem_u32(ring);
    auto issue = [&](int i) {
        unsigned dst = rbase + (unsigned)(i & 15) * 768u;
        const unsigned long long* src = mask + (size_t)i * NWORDS;
        CP8(dst + (unsigned)lane * 8u, src + lane);
        CP8(dst + (unsigned)(lane + 32) * 8u, src + lane + 32);
        if (lane < NWORDS - 64) CP8(dst + (unsigned)(lane + 64) * 8u, src + lane + 64);
        CP_COMMIT();
    };
    for (int i = 0; i < 15; i++) issue(i);

    unsigned long long cur = __shfl_sync(0xffffffffu, k0, 0);

    for (int i = 0; i < NIN; i++) {
        asm volatile("cp.async.wait_group 14;");
        if ((i & 63) == 0 && i) {
            int w = i >> 6;
            unsigned long long kw = (w < 32) ? k0 : ((w < 64) ? k1 : k2);
            cur = __shfl_sync(0xffffffffu, kw, w & 31);
        }
        bool alive = (cur >> (i & 63)) & 1ull;
        if (alive) {
            unsigned saddr = rbase + (unsigned)(i & 15) * 768u;
            unsigned long long r0, r1, r2 = 0;
            LDS64(r0, saddr + (unsigned)lane * 8u);
            LDS64(r1, saddr + (unsigned)(lane + 32) * 8u);
            if (lane < NWORDS - 64) LDS64(r2, saddr + (unsigned)(lane + 64) * 8u);
            k0 &= ~r0;
            k1 &= ~r1;
            k2 &= ~r2;
            int w = i >> 6;
            unsigned long long rw = (w < 32) ? r0 : ((w < 64) ? r1 : r2);
            rw = __shfl_sync(0xffffffffu, rw, w & 31);
            cur &= ~rw;
        }
        if (i + 15 < NIN) issue(i + 15);
    }

    int* kout = g_keep + b * NIN;
#pragma unroll 1
    for (int k = 0; k < 64; k++) {
        kout[w0 * 64 + k] = (int)((k0 >> k) & 1ull);
        kout[w1 * 64 + k] = (int)((k1 >> k) & 1ull);
        int j2 = w2 * 64 + k;
        if (w2 < NWORDS && j2 < NIN)
            kout[j2] = (int)((k2 >> k) & 1ull);
    }
}

// compact kept boxes into first 300 rows; zero-fill the rest; roi_indices
__global__ __launch_bounds__(1024) void compact_kernel(float* __restrict__ out)
{
    const int b = blockIdx.x;
    const int tid = threadIdx.x;
    __shared__ int csum[1024];

    const int base = tid * 6;
    int local[6];
    int cnt = 0;
#pragma unroll
    for (int e = 0; e < 6; e++) {
        int i = base + e;
        int k = (i < NIN) ? g_keep[b * NIN + i] : 0;
        local[e] = k;
        cnt += k;
    }
    csum[tid] = cnt;
    __syncthreads();
    for (int off = 1; off < 1024; off <<= 1) {
        int v = (tid >= off) ? csum[tid - off] : 0;
        __syncthreads();
        csum[tid] += v;
        __syncthreads();
    }
    int rank = csum[tid] - cnt;

    float* rois = out + OFS_ROIS + (size_t)b * 1200;
    for (int i = tid; i < 1200; i += 1024) rois[i] = 0.f;
    float* ridx = out + OFS_RIDX + (size_t)b * 300;
    for (int i = tid; i < 300; i += 1024) ridx[i] = (float)b;
    __syncthreads();

    int r = rank;
#pragma unroll
    for (int e = 0; e < 6; e++) {
        int i = base + e;
        if (i < NIN && local[e]) {
            if (r < NOUTB) {
                float4 bx = g_bsort4[b * NIN + i];
                rois[r * 4 + 0] = bx.x;
                rois[r * 4 + 1] = bx.y;
                rois[r * 4 + 2] = bx.z;
                rois[r * 4 + 3] = bx.w;
            }
            r++;
        }
    }
}

extern "C" void kernel_launch(void* const* d_in, const int* in_sizes, int n_in,
                              void* d_out, int out_size)
{
    const float* x       = (const float*)d_in[0];
    const float* conv_w  = (const float*)d_in[1];
    const float* conv_b  = (const float*)d_in[2];
    const float* score_w = (const float*)d_in[3];
    const float* score_b = (const float*)d_in[4];
    const float* loc_w   = (const float*)d_in[5];
    const float* loc_b   = (const float*)d_in[6];
    float* out = (float*)d_out;

    const int CONV_SMEM = 1024 + 2 * 36864;   // align slack + 2 buffer sets
    cudaFuncSetAttribute(conv_mma_kernel,
        cudaFuncAttributeMaxDynamicSharedMemorySize, CONV_SMEM);
    cudaFuncSetAttribute(sortsel_kernel,
        cudaFuncAttributeMaxDynamicSharedMemorySize, NSEL * 8);

    wsplit_kernel<<<4608, 256>>>(conv_w);
    xsplit_kernel<<<8192, 256>>>(x);
    zerohist_kernel<<<256, 1024>>>();
    conv_mma_kernel<<<dim3(8, 128), 256, CONV_SMEM>>>(x, conv_b);
    heads_kernel<<<128, 128>>>(score_w, score_b, loc_w, loc_b, out);
    select_kernel<<<BATCH, 1024>>>();
    compact_sel_kernel<<<dim3(144, BATCH), 256>>>();
    sortsel_kernel<<<BATCH, 1024, NSEL * 8>>>();
    nmsmask_kernel<<<dim3(750, BATCH), 256>>>();
    nmsscan_kernel<<<BATCH, 32>>>();
    compact_kernel<<<BATCH, 1024>>>(out);
}

// round 17
// speedup vs baseline: 7.0638x; 1.2645x over previous
#include <cuda_runtime.h>
#include <cuda_fp16.h>
#include <math.h>

#define A_TOTAL 36864
#define NIN     6000
#define NOUTB   300
#define BATCH   4
#define NSEL    16384
#define NWORDS  94

// output layout (float32, concatenated reference tuple)
#define OFS_SCORES 0
#define OFS_LOCS   294912
#define OFS_ROIS   884736
#define OFS_RIDX   889536
#define OFS_ANCH   890736

#define TSTRIDE (9u * 8u * 512u * 32u)   // u32 elements per split-term plane

// scratch (device globals; no allocation allowed)
__device__ float  g_h[BATCH * 512 * 4096];
__device__ unsigned g_wsplit[2 * 9 * 8 * 512 * 32];   // [term][kk][cic][co][j2] fp16x2
__device__ unsigned short g_xs0[BATCH * 4096 * 512];  // channel-last fp16 planes
__device__ unsigned short g_xs1[BATCH * 4096 * 512];  // residual * 2^11
__device__ float4 g_boxes4[BATCH * A_TOTAL];
__device__ unsigned long long g_keys[BATCH * A_TOTAL];
__device__ unsigned g_hist[BATCH * 65536];
__device__ int    g_thr[BATCH];
__device__ int    g_cnt[BATCH];
__device__ unsigned long long g_sel[BATCH * NSEL];
__device__ float4 g_bsort4[BATCH * NIN];
__device__ float  g_areas[BATCH * NIN];
__device__ int    g_keep[BATCH * NIN];
__device__ unsigned long long g_nmsmask[(size_t)BATCH * NIN * NWORDS];

// ---------------------------------------------------------------------------
// helpers
// ---------------------------------------------------------------------------
#define SWZ64(o) ((o) ^ (((o) >> 3) & 0x30))

static __device__ __forceinline__ unsigned smem_u32(const void* p) {
    unsigned a;
    asm("{ .reg .u64 t; cvta.to.shared.u64 t, %1; cvt.u32.u64 %0, t; }"
        : "=r"(a) : "l"(p));
    return a;
}
// no "memory" clobber — __syncthreads() is the fence
#define STS32(addr, val) \
    asm volatile("st.shared.b32 [%0], %1;" :: "r"(addr), "r"(val))

#define LDS64(d, a) \
    asm volatile("ld.shared.b64 %0, [%1];" : "=l"(d) : "r"(a))

#define CP8(dst, src) \
    asm volatile("cp.async.ca.shared.global [%0], [%1], 8;" \
                 :: "r"(dst), "l"(src))
#define CP16(dst, src) \
    asm volatile("cp.async.cg.shared.global [%0], [%1], 16;" \
                 :: "r"(dst), "l"(src))
#define CP16Z(dst, src, sz) \
    asm volatile("cp.async.cg.shared.global [%0], [%1], 16, %2;" \
                 :: "r"(dst), "l"(src), "r"(sz))
#define CP_COMMIT() asm volatile("cp.async.commit_group;")
#define CP_WAIT0()  asm volatile("cp.async.wait_group 0;")

#define LDSM_X4(r0, r1, r2, r3, addr) \
    asm volatile("ldmatrix.sync.aligned.m8n8.x4.shared.b16 {%0,%1,%2,%3}, [%4];" \
                 : "=r"(r0), "=r"(r1), "=r"(r2), "=r"(r3) : "r"(addr))

#define MMAF16(d0, d1, d2, d3, a0, a1, a2, a3, b0, b1) \
    asm volatile("mma.sync.aligned.m16n8k16.row.col.f32.f16.f16.f32 " \
                 "{%0,%1,%2,%3}, {%4,%5,%6,%7}, {%8,%9}, {%0,%1,%2,%3};" \
                 : "+f"(d0), "+f"(d1), "+f"(d2), "+f"(d3) \
                 : "r"(a0), "r"(a1), "r"(a2), "r"(a3), "r"(b0), "r"(b1))

// fp16 2-way split: v = h0 + h1 * 2^-11 (h1 pre-scaled by 2^11)
static __device__ __forceinline__ void split2h(float v, unsigned short o[2]) {
    __half h0 = __float2half_rn(v);
    float r = (v - __half2float(h0)) * 2048.f;
    __half h1 = __float2half_rn(r);
    o[0] = __half_as_ushort(h0);
    o[1] = __half_as_ushort(h1);
}

// ---------------------------------------------------------------------------
// weight split precompute: w[co][ci][kk] -> 2 fp16 planes [kk][cic][co][j2]
// ---------------------------------------------------------------------------
__global__ void wsplit_kernel(const float* __restrict__ w)
{
    int idx = blockIdx.x * 256 + threadIdx.x;   // 9*8*512*32 = 1,179,648 exact
    int j2  = idx & 31;
    int co  = (idx >> 5) & 511;
    int cic = (idx >> 14) & 7;
    int kk  = idx >> 17;
    if (kk >= 9) return;
    int ci = cic * 64 + j2 * 2;
    float v0 = w[((size_t)co * 512 + ci) * 9 + kk];
    float v1 = w[((size_t)co * 512 + ci + 1) * 9 + kk];
    unsigned short h[2], g[2];
    split2h(v0, h);
    split2h(v1, g);
    unsigned base = (((unsigned)kk * 8 + cic) * 512 + co) * 32 + j2;
#pragma unroll
    for (int t = 0; t < 2; t++)
        g_wsplit[t * TSTRIDE + base] = (unsigned)h[t] | ((unsigned)g[t] << 16);
}

// ---------------------------------------------------------------------------
// input split precompute: x[b][ci][y][x] f32 -> channel-last fp16 planes
// ---------------------------------------------------------------------------
__global__ __launch_bounds__(256) void xsplit_kernel(const float* __restrict__ x)
{
    __shared__ float t[32][33];
    const int bid = blockIdx.x;          // 4 * 16 * 128 = 8192 blocks
    const int pt  = bid & 127;           // pixel tile (32 px)
    const int ct  = (bid >> 7) & 15;     // ci tile (32 ci)
    const int b   = bid >> 11;
    const int tid = threadIdx.x;

    const float* xp = x + ((size_t)b * 512 + ct * 32) * 4096 + pt * 32;
#pragma unroll
    for (int k = 0; k < 4; k++) {
        int l = tid + k * 256;
        int ci_l = l >> 5, px_l = l & 31;
        t[ci_l][px_l] = xp[(size_t)ci_l * 4096 + px_l];
    }
    __syncthreads();
#pragma unroll
    for (int k = 0; k < 4; k++) {
        int l = tid + k * 256;
        int px_l = l >> 5, ci_l = l & 31;
        float v = t[ci_l][px_l];
        unsigned short h[2];
        split2h(v, h);
        size_t o = ((size_t)b * 4096 + pt * 32 + px_l) * 512 + ct * 32 + ci_l;
        g_xs0[o] = h[0];
        g_xs1[o] = h[1];
    }
}

__global__ void zerohist_kernel()
{
    g_hist[blockIdx.x * 1024 + threadIdx.x] = 0u;
}

// ---------------------------------------------------------------------------
// 3x3 conv 512->512 + bias + relu via mma.sync fp16 3-term emulated-fp32:
//   w*x = w0*x0 + 2^-11 * (w0*x1' + w1'*x0),   (x1', w1' pre-scaled by 2^11)
// CTA: 256 threads / 8 warps, M=64 co, N=128 px. Warp tile m32n32.
// 144 chunks of 32 ci at fixed (dy,dx); SW64 tiles; double-buffered cp.async;
// 2 CTAs/SM. Per chunk: 16 LDSM, 48 MMA. Two partials P_A (chain 2) and
// P_B (chain 4) folded per chunk with rn FADD / exact-scale FMA.
// ---------------------------------------------------------------------------
__global__ __launch_bounds__(256, 2) void conv_mma_kernel(
    const float* __restrict__ x, const float* __restrict__ bias)
{
    extern __shared__ __align__(16) char dsm[];
    const unsigned raw  = smem_u32(dsm);
    const unsigned base = (raw + 1023u) & ~1023u;  // 1024-aligned tiles

    const int tid = threadIdx.x;
    const int wid = tid >> 5;
    const int lid = tid & 31;
    const int m0  = blockIdx.x * 64;
    const int b   = blockIdx.y >> 5;
    const int y0  = (blockIdx.y & 31) * 2;

    const int mh = wid >> 2;            // co block of 32 (0..1)
    const int nq = wid & 3;             // px block of 32 (0..3)
    const int rlow = lid & 15;
    const int chalf = (lid >> 4) * 16;
    const float SC = 4.8828125e-4f;     // 2^-11, exact

    float acc[2][4][4], PA[2][4][4], PB[2][4][4];
#pragma unroll
    for (int i = 0; i < 2; i++)
#pragma unroll
        for (int j = 0; j < 4; j++)
#pragma unroll
            for (int r = 0; r < 4; r++) {
                acc[i][j][r] = 0.f; PA[i][j][r] = 0.f; PB[i][j][r] = 0.f;
            }

    // set layout (stride 24576): B0 @ 0 (8K), B1 @ 8K, A0 @ 16K (4K), A1 @ 20K
    auto stageAB = [&](int c, int s) {
        const int kk   = c >> 4;           // 0..8
        const int sub  = c & 15;           // 32-ci subchunk
        const int cic  = sub >> 1;
        const int half = sub & 1;
        const int dy   = kk / 3, dx = kk - dy * 3;
        const int ci0  = sub * 32;
        const unsigned sb = base + (unsigned)s * 24576u;
        // A: 64 co x 64B per term (copy from pre-split weights)
        const unsigned* wp = g_wsplit
            + ((unsigned)(kk * 8 + cic) * 512 + m0) * 32 + half * 16;
#pragma unroll
        for (int it = 0; it < 2; it++) {
            int idx = tid + it * 256;      // 0..511
            int term = idx >> 8;
            int r = idx & 255;
            int co = r >> 2, seg = r & 3;
            unsigned off = SWZ64((unsigned)(co * 64 + seg * 16));
            CP16(sb + 16384u + (unsigned)term * 4096u + off,
                 wp + (unsigned)term * TSTRIDE + co * 32 + seg * 4);
        }
        // B: 128 px x 64B per term (channel-last pre-split input)
#pragma unroll
        for (int it = 0; it < 4; it++) {
            int idx = tid + it * 256;      // 0..1023
            int term = idx >> 9;
            int r = idx & 511;
            int px = r >> 2, seg = r & 3;
            int yy = y0 + (px >> 6) + dy - 1;
            int xx = (px & 63) + dx - 1;
            bool ok = ((unsigned)yy < 64u) && ((unsigned)xx < 64u);
            int yc = ok ? yy : 0, xc = ok ? xx : 0;
            size_t po = ((size_t)b * 4096 + (size_t)yc * 64 + xc) * 512
                        + ci0 + seg * 8;
            const unsigned short* plane = (term == 0) ? g_xs0 : g_xs1;
            unsigned off = SWZ64((unsigned)(px * 64 + seg * 16));
            CP16Z(sb + (unsigned)term * 8192u + off, plane + po, ok ? 16 : 0);
        }
    };

    // 8 MMAs of one m32n32 term-pair into partial P
    auto mma_pair = [&](float P[2][4][4], const unsigned* A, const unsigned* B) {
#pragma unroll
        for (int mt = 0; mt < 2; mt++)
#pragma unroll
            for (int bn = 0; bn < 2; bn++) {
                MMAF16(P[mt][bn*2][0], P[mt][bn*2][1], P[mt][bn*2][2], P[mt][bn*2][3],
                       A[mt*4+0], A[mt*4+1], A[mt*4+2], A[mt*4+3],
                       B[bn*4+0], B[bn*4+2]);
                MMAF16(P[mt][bn*2+1][0], P[mt][bn*2+1][1], P[mt][bn*2+1][2], P[mt][bn*2+1][3],
                       A[mt*4+0], A[mt*4+1], A[mt*4+2], A[mt*4+3],
                       B[bn*4+1], B[bn*4+3]);
            }
    };

    stageAB(0, 0);
    CP_COMMIT();
    CP_WAIT0();
    __syncthreads();

    for (int c = 0; c < 144; c++) {
        const int s = c & 1;
        if (c + 1 < 144) {
            stageAB(c + 1, s ^ 1);
            CP_COMMIT();
        }

        const unsigned sb  = base + (unsigned)s * 24576u;
        const unsigned B0b = sb, B1b = sb + 8192u;
        const unsigned A0b = sb + 16384u, A1b = sb + 20480u;
#pragma unroll
        for (int ks = 0; ks < 2; ks++) {
            const unsigned aoff0 = SWZ64((unsigned)((mh * 32 + rlow) * 64 + ks * 32 + chalf));
            const unsigned aoff1 = SWZ64((unsigned)((mh * 32 + 16 + rlow) * 64 + ks * 32 + chalf));
            const unsigned boff0 = SWZ64((unsigned)((nq * 32 + rlow) * 64 + ks * 32 + chalf));
            const unsigned boff1 = SWZ64((unsigned)((nq * 32 + 16 + rlow) * 64 + ks * 32 + chalf));
            unsigned A[8], B0[8], B1[8];
            // a0, b0
            LDSM_X4(A[0], A[1], A[2], A[3], A0b + aoff0);
            LDSM_X4(A[4], A[5], A[6], A[7], A0b + aoff1);
            LDSM_X4(B0[0], B0[1], B0[2], B0[3], B0b + boff0);
            LDSM_X4(B0[4], B0[5], B0[6], B0[7], B0b + boff1);
            mma_pair(PA, A, B0);                    // a0*b0
            // b1
            LDSM_X4(B1[0], B1[1], B1[2], B1[3], B1b + boff0);
            LDSM_X4(B1[4], B1[5], B1[6], B1[7], B1b + boff1);
            mma_pair(PB, A, B1);                    // a0*b1'
            // a1 (overwrite A)
            LDSM_X4(A[0], A[1], A[2], A[3], A1b + aoff0);
            LDSM_X4(A[4], A[5], A[6], A[7], A1b + aoff1);
            mma_pair(PB, A, B0);                    // a1'*b0
        }
        // fold partials: acc += PA; acc += PB * 2^-11 (exact scale)
#pragma unroll
        for (int i = 0; i < 2; i++)
#pragma unroll
            for (int j = 0; j < 4; j++)
#pragma unroll
                for (int r = 0; r < 4; r++) {
                    acc[i][j][r] += PA[i][j][r];
                    acc[i][j][r] = fmaf(PB[i][j][r], SC, acc[i][j][r]);
                    PA[i][j][r] = 0.f; PB[i][j][r] = 0.f;
                }

        if (c + 1 < 144) CP_WAIT0();
        __syncthreads();
    }

    // epilogue: accs -> bias+relu -> smem transpose [co][px] (row stride 132 f32)
    {
        const int gr = lid >> 2;
        const int qc = lid & 3;
#pragma unroll
        for (int mt = 0; mt < 2; mt++) {
#pragma unroll
            for (int hi = 0; hi < 2; hi++) {
                int co_l = mh * 32 + mt * 16 + hi * 8 + gr;   // 0..63
                float bb = bias[m0 + co_l];
                unsigned trow = base + (unsigned)co_l * 528u;
#pragma unroll
                for (int nn = 0; nn < 4; nn++) {
#pragma unroll
                    for (int lo = 0; lo < 2; lo++) {
                        int px = nq * 32 + nn * 8 + qc * 2 + lo;
                        float v = acc[mt][nn][hi * 2 + lo] + bb;
                        v = v > 0.f ? v : 0.f;
                        STS32(trow + (unsigned)px * 4u, __float_as_uint(v));
                    }
                }
            }
        }
    }
    __syncthreads();

    // coalesced write-out: g_h[b][m0+co][y0 + px/64][px%64]
    for (int idx = tid; idx < 2048; idx += 256) {
        int co = idx >> 5;                 // 0..63
        int p4 = (idx & 31) * 4;
        unsigned a0, a1, a2, a3;
        asm volatile("ld.shared.v4.b32 {%0,%1,%2,%3}, [%4];"
                     : "=r"(a0), "=r"(a1), "=r"(a2), "=r"(a3)
                     : "r"(base + (unsigned)co * 528u + (unsigned)p4 * 4u));
        float* dst = g_h + (((size_t)b * 512 + m0 + co) * 64 + y0 + (p4 >> 6)) * 64
                     + (p4 & 63);
        *(float4*)dst = make_float4(__uint_as_float(a0), __uint_as_float(a1),
                                    __uint_as_float(a2), __uint_as_float(a3));
    }
}

// ---------------------------------------------------------------------------
// 1x1 heads + softmax fg + box decode + sort keys + score-bucket histogram
// ---------------------------------------------------------------------------
__global__ __launch_bounds__(128) void heads_kernel(
    const float* __restrict__ sw, const float* __restrict__ sb,
    const float* __restrict__ lw, const float* __restrict__ lb,
    float* __restrict__ out)
{
    __shared__ float ws[64 * 54];
    const int tid = threadIdx.x;
    const int pg  = blockIdx.x * 128 + tid;
    const int b   = pg >> 12;
    const int pix = pg & 4095;

    float acc[54];
#pragma unroll
    for (int c = 0; c < 54; c++) acc[c] = 0.f;

    for (int cc = 0; cc < 512; cc += 64) {
        for (int idx = tid; idx < 64 * 54; idx += 128) {
            int ci = idx / 54;
            int c  = idx - ci * 54;
            ws[idx] = (c < 18) ? sw[c * 512 + cc + ci]
                               : lw[(c - 18) * 512 + cc + ci];
        }
        __syncthreads();
#pragma unroll 4
        for (int ci = 0; ci < 64; ci++) {
            float v = g_h[((size_t)(b * 512 + cc + ci)) * 4096 + pix];
#pragma unroll
            for (int c = 0; c < 54; c++) acc[c] += v * ws[ci * 54 + c];
        }
        __syncthreads();
    }

    const int y  = pix >> 6;
    const int xq = pix & 63;
    const float sy = (float)(y * 16);
    const float sx = (float)(xq * 16);

#pragma unroll
    for (int k = 0; k < 9; k++) {
        const double RR[3] = {0.5, 1.0, 2.0};
        const double SS[3] = {8.0, 16.0, 32.0};
        double rr = RR[k / 3], ss = SS[k % 3];
        double hh = 16.0 * ss * sqrt(rr);
        double wd = 16.0 * ss * sqrt(1.0 / rr);
        float by1 = (float)(8.0 - hh * 0.5), bx1 = (float)(8.0 - wd * 0.5);
        float by2 = (float)(8.0 + hh * 0.5), bx2 = (float)(8.0 + wd * 0.5);
        float ay1 = sy + by1, ax1 = sx + bx1, ay2 = sy + by2, ax2 = sx + bx2;

        const int a = pix * 9 + k;
        if (b == 0) {
            float* ap = out + OFS_ANCH + (size_t)a * 4;
            ap[0] = ay1; ap[1] = ax1; ap[2] = ay2; ap[3] = ax2;
        }

        float s0 = acc[k * 2 + 0] + sb[k * 2 + 0];
        float s1 = acc[k * 2 + 1] + sb[k * 2 + 1];
        out[OFS_SCORES + (size_t)b * 73728 + (size_t)a * 2 + 0] = s0;
        out[OFS_SCORES + (size_t)b * 73728 + (size_t)a * 2 + 1] = s1;

        float d0 = acc[18 + k * 4 + 0] + lb[k * 4 + 0];
        float d1 = acc[18 + k * 4 + 1] + lb[k * 4 + 1];
        float d2 = acc[18 + k * 4 + 2] + lb[k * 4 + 2];
        float d3 = acc[18 + k * 4 + 3] + lb[k * 4 + 3];
        float* lp = out + OFS_LOCS + (size_t)b * 147456 + (size_t)a * 4;
        lp[0] = d0; lp[1] = d1; lp[2] = d2; lp[3] = d3;

        float ah = ay2 - ay1, aw = ax2 - ax1;
        float cy = ay1 + 0.5f * ah, cx = ax1 + 0.5f * aw;
        float cty = d0 * ah + cy, ctx = d1 * aw + cx;
        float th = expf(d2) * ah, tw = expf(d3) * aw;
        float cy1 = fminf(fmaxf(cty - 0.5f * th, 0.f), 1024.f);
        float cy2 = fminf(fmaxf(cty + 0.5f * th, 0.f), 1024.f);
        float cx1 = fminf(fmaxf(ctx - 0.5f * tw, 0.f), 1024.f);
        float cx2 = fminf(fmaxf(ctx + 0.5f * tw, 0.f), 1024.f);
        bool valid = (cy2 - cy1 >= 16.f) && (cx2 - cx1 >= 16.f);

        float m = fmaxf(s0, s1);
        float e0 = expf(s0 - m), e1 = expf(s1 - m);
        float p1 = e1 / (e0 + e1);

        g_boxes4[(size_t)b * A_TOTAL + a] = make_float4(cy1, cx1, cy2, cx2);

        unsigned long long key;
        if (valid) {
            unsigned u = __float_as_uint(p1);
            u = (u & 0x80000000u) ? ~u : (u | 0x80000000u);
            key = ((unsigned long long)(~u) << 32) | (unsigned)a;
        } else {
            key = (0xFF800000ull << 32) | (unsigned)a;  // -inf score
        }
        g_keys[(size_t)b * A_TOTAL + a] = key;
        atomicAdd(&g_hist[b * 65536 + (unsigned)(key >> 48)], 1u);
    }
}

// find bucket threshold covering rank NIN; also reset count + pad sel buffer
__global__ __launch_bounds__(1024) void select_kernel()
{
    const int b = blockIdx.x, tid = threadIdx.x;
    __shared__ int part[1024];
    const unsigned* h = g_hist + b * 65536;
    int s = 0;
    for (int k = 0; k < 64; k++) s += (int)h[tid * 64 + k];
    part[tid] = s;
    __syncthreads();
    for (int off = 1; off < 1024; off <<= 1) {
        int v = (tid >= off) ? part[tid - off] : 0;
        __syncthreads();
        part[tid] += v;
        __syncthreads();
    }
    int incl = part[tid];
    int excl = incl - s;
    if (excl < NIN && incl >= NIN) {
        int c = excl, T = tid * 64 + 63;
        for (int k = 0; k < 64; k++) {
            c += (int)h[tid * 64 + k];
            if (c >= NIN) { T = tid * 64 + k; break; }
        }
        g_thr[b] = T;
    }
    if (tid == 0) g_cnt[b] = 0;
    for (int i = tid; i < NSEL; i += 1024) g_sel[b * NSEL + i] = ~0ull;
}

__global__ void compact_sel_kernel()
{
    int i = blockIdx.x * 256 + threadIdx.x;
    int b = blockIdx.y;
    if (i >= A_TOTAL) return;
    unsigned long long key = g_keys[(size_t)b * A_TOTAL + i];
    if ((int)(unsigned)(key >> 48) <= g_thr[b]) {
        int p = atomicAdd(&g_cnt[b], 1);
        if (p < NSEL) g_sel[b * NSEL + p] = key;
    }
}

// per-batch smem bitonic sort of <=16384 selected keys, then gather top-6000
__global__ __launch_bounds__(1024) void sortsel_kernel()
{
    const int b = blockIdx.x, tid = threadIdx.x;
    extern __shared__ unsigned long long s[];
    for (int i = tid; i < NSEL; i += 1024) s[i] = g_sel[b * NSEL + i];
    __syncthreads();
    for (int k = 2; k <= NSEL; k <<= 1) {
        for (int j = k >> 1; j > 0; j >>= 1) {
            for (int t = tid; t < NSEL; t += 1024) {
                int ixj = t ^ j;
                if (ixj > t) {
                    unsigned long long A = s[t], B = s[ixj];
                    bool up = ((t & k) == 0);
                    if ((A > B) == up) { s[t] = B; s[ixj] = A; }
                }
            }
            __syncthreads();
        }
    }
    for (int i = tid; i < NIN; i += 1024) {
        unsigned long long key = s[i];
        unsigned idx = (unsigned)key;
        float4 bx = g_boxes4[(size_t)b * A_TOTAL + idx];
        g_bsort4[b * NIN + i] = bx;
        g_areas[b * NIN + i] = (bx.z - bx.x) * (bx.w - bx.y);
        g_keep[b * NIN + i] = (int)((key >> 63) == 0);
    }
}

// ---------------------------------------------------------------------------
// NMS stage 1 (parallel): suppression bitmask rows.
// ---------------------------------------------------------------------------
__global__ __launch_bounds__(256) void nmsmask_kernel()
{
    const int b = blockIdx.y;
    const int i = blockIdx.x * 8 + (threadIdx.x >> 5);
    const int lane = threadIdx.x & 31;
    if (i >= NIN) return;
    const float4* bx = g_bsort4 + (size_t)b * NIN;
    const float*  ar = g_areas + b * NIN;
    float4 bi = bx[i];
    float  ai = ar[i];
    unsigned long long* row = g_nmsmask + ((size_t)b * NIN + i) * NWORDS;
    unsigned mlo = 0;
#pragma unroll 4
    for (int sc = 0; sc < 2 * NWORDS; sc++) {     // 188 subchunks of 32
        int j = sc * 32 + lane;
        bool sup = false;
        if (sc * 32 + 31 > i) {                   // subchunk contains j > i
            if (j > i && j < NIN) {
                float4 bj = bx[j];
                float yy1 = fmaxf(bi.x, bj.x);
                float xx1 = fmaxf(bi.y, bj.y);
                float yy2 = fminf(bi.z, bj.z);
                float xx2 = fminf(bi.w, bj.w);
                float inter = fmaxf(yy2 - yy1, 0.f) * fmaxf(xx2 - xx1, 0.f);
                float iou = inter / (ai + ar[j] - inter + 1e-9f);
                sup = iou > 0.7f;
            }
        }
        unsigned m = __ballot_sync(0xffffffffu, sup);
        if (sc & 1) {
            if (lane == 0)
                row[sc >> 1] = (unsigned long long)mlo
                             | ((unsigned long long)m << 32);
        } else {
            mlo = m;
        }
    }
}

// ---------------------------------------------------------------------------
// NMS stage 2 (serial, 1 warp per batch): greedy scan over register bitmap.
// ---------------------------------------------------------------------------
__global__ __launch_bounds__(32) void nmsscan_kernel()
{
    __shared__ __align__(16) unsigned long long ring[16][96];
    const int b = blockIdx.x;
    const int lane = threadIdx.x;
    const unsigned long long* mask = g_nmsmask + (size_t)b * NIN * NWORDS;
    const int* kin = g_keep + b * NIN;

    const int w0 = lane, w1 = lane + 32, w2 = lane + 64;
    unsigned long long k0 = 0, k1 = 0, k2 = 0;
#pragma unroll 1
    for (int k = 0; k < 64; k++) {
        k0 |= (unsigned long long)(kin[w0 * 64 + k] & 1) << k;
        k1 |= (unsigned long long)(kin[w1 * 64 + k] & 1) << k;
        int j2 = w2 * 64 + k;
        if (w2 < NWORDS && j2 < NIN)
            k2 |= (unsigned long long)(kin[j2] & 1) << k;
    }

    const unsigned rbase = smem_u32(ring);
    auto issue = [&](int i) {
        unsigned dst = rbase + (unsigned)(i & 15) * 768u;
        const unsigned long long* src = mask + (size_t)i * NWORDS;
        CP8(dst + (unsigned)lane * 8u, src + lane);
        CP8(dst + (unsigned)(lane + 32) * 8u, src + lane + 32);
        if (lane < NWORDS - 64) CP8(dst + (unsigned)(lane + 64) * 8u, src + lane + 64);
        CP_COMMIT();
    };
    for (int i = 0; i < 15; i++) issue(i);

    unsigned long long cur = __shfl_sync(0xffffffffu, k0, 0);

    for (int i = 0; i < NIN; i++) {
        asm volatile("cp.async.wait_group 14;");
        if ((i & 63) == 0 && i) {
            int w = i >> 6;
            unsigned long long kw = (w < 32) ? k0 : ((w < 64) ? k1 : k2);
            cur = __shfl_sync(0xffffffffu, kw, w & 31);
        }
        bool alive = (cur >> (i & 63)) & 1ull;
        if (alive) {
            unsigned saddr = rbase + (unsigned)(i & 15) * 768u;
            unsigned long long r0, r1, r2 = 0;
            LDS64(r0, saddr + (unsigned)lane * 8u);
            LDS64(r1, saddr + (unsigned)(lane + 32) * 8u);
            if (lane < NWORDS - 64) LDS64(r2, saddr + (unsigned)(lane + 64) * 8u);
            k0 &= ~r0;
            k1 &= ~r1;
            k2 &= ~r2;
            int w = i >> 6;
            unsigned long long rw = (w < 32) ? r0 : ((w < 64) ? r1 : r2);
            rw = __shfl_sync(0xffffffffu, rw, w & 31);
            cur &= ~rw;
        }
        if (i + 15 < NIN) issue(i + 15);
    }

    int* kout = g_keep + b * NIN;
#pragma unroll 1
    for (int k = 0; k < 64; k++) {
        kout[w0 * 64 + k] = (int)((k0 >> k) & 1ull);
        kout[w1 * 64 + k] = (int)((k1 >> k) & 1ull);
        int j2 = w2 * 64 + k;
        if (w2 < NWORDS && j2 < NIN)
            kout[j2] = (int)((k2 >> k) & 1ull);
    }
}

// compact kept boxes into first 300 rows; zero-fill the rest; roi_indices
__global__ __launch_bounds__(1024) void compact_kernel(float* __restrict__ out)
{
    const int b = blockIdx.x;
    const int tid = threadIdx.x;
    __shared__ int csum[1024];

    const int base = tid * 6;
    int local[6];
    int cnt = 0;
#pragma unroll
    for (int e = 0; e < 6; e++) {
        int i = base + e;
        int k = (i < NIN) ? g_keep[b * NIN + i] : 0;
        local[e] = k;
        cnt += k;
    }
    csum[tid] = cnt;
    __syncthreads();
    for (int off = 1; off < 1024; off <<= 1) {
        int v = (tid >= off) ? csum[tid - off] : 0;
        __syncthreads();
        csum[tid] += v;
        __syncthreads();
    }
    int rank = csum[tid] - cnt;

    float* rois = out + OFS_ROIS + (size_t)b * 1200;
    for (int i = tid; i < 1200; i += 1024) rois[i] = 0.f;
    float* ridx = out + OFS_RIDX + (size_t)b * 300;
    for (int i = tid; i < 300; i += 1024) ridx[i] = (float)b;
    __syncthreads();

    int r = rank;
#pragma unroll
    for (int e = 0; e < 6; e++) {
        int i = base + e;
        if (i < NIN && local[e]) {
            if (r < NOUTB) {
                float4 bx = g_bsort4[b * NIN + i];
                rois[r * 4 + 0] = bx.x;
                rois[r * 4 + 1] = bx.y;
                rois[r * 4 + 2] = bx.z;
                rois[r * 4 + 3] = bx.w;
            }
            r++;
        }
    }
}

extern "C" void kernel_launch(void* const* d_in, const int* in_sizes, int n_in,
                              void* d_out, int out_size)
{
    const float* x       = (const float*)d_in[0];
    const float* conv_w  = (const float*)d_in[1];
    const float* conv_b  = (const float*)d_in[2];
    const float* score_w = (const float*)d_in[3];
    const float* score_b = (const float*)d_in[4];
    const float* loc_w   = (const float*)d_in[5];
    const float* loc_b   = (const float*)d_in[6];
    float* out = (float*)d_out;

    const int CONV_SMEM = 1024 + 2 * 24576;   // align slack + 2 buffer sets
    cudaFuncSetAttribute(conv_mma_kernel,
        cudaFuncAttributeMaxDynamicSharedMemorySize, CONV_SMEM);
    cudaFuncSetAttribute(sortsel_kernel,
        cudaFuncAttributeMaxDynamicSharedMemorySize, NSEL * 8);

    wsplit_kernel<<<4608, 256>>>(conv_w);
    xsplit_kernel<<<8192, 256>>>(x);
    zerohist_kernel<<<256, 1024>>>();
    conv_mma_kernel<<<dim3(8, 128), 256, CONV_SMEM>>>(x, conv_b);
    heads_kernel<<<128, 128>>>(score_w, score_b, loc_w, loc_b, out);
    select_kernel<<<BATCH, 1024>>>();
    compact_sel_kernel<<<dim3(144, BATCH), 256>>>();
    sortsel_kernel<<<BATCH, 1024, NSEL * 8>>>();
    nmsmask_kernel<<<dim3(750, BATCH), 256>>>();
    nmsscan_kernel<<<BATCH, 32>>>();
    compact_kernel<<<BATCH, 1024>>>(out);
}